// round 2
// baseline (speedup 1.0000x reference)
#include <cuda_runtime.h>
#include <math.h>

// ---------------- problem constants ----------------
#define D_    256
#define NH_   8
#define HD_   32
#define B_    8
#define LQ_   3600
#define LIN_  4725           // 60*60 + 30*30 + 15*15
#define ROWS_ (LQ_*B_)       // 28800  (row index i = lq*B + b)
#define VROWS_ (B_*LIN_)     // 37800
#define DFF_  1024

// ---------------- scratch (device globals; no allocations) ----------------
// Q/K/V layout: [lq][h][s(=8)][d(=32)] -> contiguous 1KB tile per (lq,h)
__device__ float g_Q  [(size_t)LQ_*NH_*8*HD_];
__device__ float g_K  [(size_t)LQ_*NH_*8*HD_];
__device__ float g_Vv [(size_t)LQ_*NH_*8*HD_];
__device__ float g_ctx[(size_t)ROWS_*D_];
__device__ float g_t  [(size_t)ROWS_*D_];     // after ln2
__device__ float g_tmp[(size_t)ROWS_*D_];
__device__ float g_val[(size_t)B_*NH_*LIN_*HD_];
__device__ float g_off[(size_t)ROWS_*192];
__device__ float g_aw [(size_t)ROWS_*96];
__device__ float g_ms [(size_t)ROWS_*D_];
__device__ float g_tq [(size_t)ROWS_*D_];
__device__ float g_ffn[(size_t)ROWS_*DFF_];
__device__ float g_cb [1024];                 // per-GEMM column bias

// ---------------- column-bias precompute: cb[n] = b[n] + (n<qplimit ? W[n]·qp : 0)
__global__ void colbias_kernel(const float* __restrict__ W, const float* __restrict__ bias,
                               const float* __restrict__ qp, int qplimit, int N, int K)
{
    int n = blockIdx.x * 128 + threadIdx.x;
    if (n >= N) return;
    float s = bias[n];
    if (n < qplimit) {
        const float* w = W + (size_t)n * K;
        float acc = 0.f;
        #pragma unroll 4
        for (int k = 0; k < K; k += 4) {
            float4 wv = *(const float4*)(w + k);
            float4 qv = *(const float4*)(qp + k);
            acc += wv.x*qv.x + wv.y*qv.y + wv.z*qv.z + wv.w*qv.w;
        }
        s += acc;
    }
    g_cb[n] = s;
}

// ---------------- generic NT SGEMM: C[m,n] = sum_k A[m,k]*W[n,k] + cb[n] ----------------
// MODE 0: plain store to C     MODE 1: relu store to C
// MODE 2: QKV scatter          MODE 3: value scatter
#define TBM 64
#define TBN 64
#define TBK 16
template<int MODE>
__global__ void __launch_bounds__(256)
gemm_nt(const float* __restrict__ A, const float* __restrict__ W,
        float* __restrict__ C, int M, int N, int K)
{
    __shared__ float As[TBK][TBM + 4];
    __shared__ float Ws[TBK][TBN + 4];
    int tid = threadIdx.x;
    int tx = tid & 15, ty = tid >> 4;
    int m0 = blockIdx.x * TBM, n0 = blockIdx.y * TBN;

    float acc[4][4];
    #pragma unroll
    for (int i = 0; i < 4; i++)
        #pragma unroll
        for (int j = 0; j < 4; j++) acc[i][j] = 0.f;

    int r  = tid >> 2;          // 0..63
    int kk = (tid & 3) * 4;     // 0,4,8,12

    for (int k0 = 0; k0 < K; k0 += TBK) {
        int gm = m0 + r;
        float4 va = (gm < M) ? *(const float4*)(A + (size_t)gm * K + k0 + kk)
                             : make_float4(0.f,0.f,0.f,0.f);
        As[kk+0][r] = va.x; As[kk+1][r] = va.y; As[kk+2][r] = va.z; As[kk+3][r] = va.w;
        int gn = n0 + r;
        float4 vw = (gn < N) ? *(const float4*)(W + (size_t)gn * K + k0 + kk)
                             : make_float4(0.f,0.f,0.f,0.f);
        Ws[kk+0][r] = vw.x; Ws[kk+1][r] = vw.y; Ws[kk+2][r] = vw.z; Ws[kk+3][r] = vw.w;
        __syncthreads();
        #pragma unroll
        for (int k = 0; k < TBK; k++) {
            float a[4], b[4];
            *(float4*)a = *(const float4*)&As[k][ty*4];
            *(float4*)b = *(const float4*)&Ws[k][tx*4];
            #pragma unroll
            for (int i = 0; i < 4; i++)
                #pragma unroll
                for (int j = 0; j < 4; j++)
                    acc[i][j] = fmaf(a[i], b[j], acc[i][j]);
        }
        __syncthreads();
    }

    #pragma unroll
    for (int i = 0; i < 4; i++) {
        int m = m0 + ty*4 + i;
        if (m >= M) continue;
        #pragma unroll
        for (int j = 0; j < 4; j++) {
            int n = n0 + tx*4 + j;
            if (n >= N) continue;
            float v = acc[i][j] + g_cb[n];
            if (MODE == 1) v = fmaxf(v, 0.f);
            if (MODE == 0 || MODE == 1) {
                C[(size_t)m * N + n] = v;
            } else if (MODE == 2) {
                // m = lq*B + b ; n = part*256 + h*32 + d
                int lq = m >> 3, b = m & 7;
                int part = n >> 8, h = (n >> 5) & 7, d = n & 31;
                size_t o = ((((size_t)lq * NH_ + h) * 8) + b) * HD_ + d;
                if (part == 0)      g_Q[o]  = v;
                else if (part == 1) g_K[o]  = v;
                else                g_Vv[o] = v;
            } else { // MODE 3
                int b = m / LIN_, lin = m - b * LIN_;
                int h = n >> 5, d = n & 31;
                g_val[(((size_t)(b*NH_ + h)) * LIN_ + lin) * HD_ + d] = v;
            }
        }
    }
}

// ---------------- self-attention over the 8-token axis ----------------
// For each (lq, h): 8 queries x 8 keys x 32 dims. One thread per (lq,h,s).
// Block: 128 threads = 2 lq values. K/V tiles staged in smem.
#define ALQ 2
__global__ void __launch_bounds__(128)
attn_kernel()
{
    __shared__ float Ks[ALQ * NH_ * 8 * HD_];   // 2048*ALQ floats
    __shared__ float Vs[ALQ * NH_ * 8 * HD_];

    int lq0 = blockIdx.x * ALQ;
    int t = threadIdx.x;

    // cooperative stage: ALQ*2048 floats each for K and V (contiguous)
    const float4* kg = (const float4*)(g_K  + (size_t)lq0 * NH_ * 8 * HD_);
    const float4* vg = (const float4*)(g_Vv + (size_t)lq0 * NH_ * 8 * HD_);
    #pragma unroll
    for (int f = 0; f < ALQ * NH_ * 8 * HD_ / 4 / 128; f++) {
        int idx = f * 128 + t;
        ((float4*)Ks)[idx] = kg[idx];
        ((float4*)Vs)[idx] = vg[idx];
    }
    __syncthreads();

    int lql = t >> 6;            // 0..ALQ-1
    int r   = t & 63;
    int h   = r >> 3;            // 0..7
    int s   = r & 7;             // query index within the 8-token axis
    int lq  = lq0 + lql;

    const float scale = 0.17677669529663687f;  // 1/sqrt(32)

    // load this thread's query row (32 floats)
    float qr[HD_];
    {
        const float* Qp = g_Q + ((((size_t)lq * NH_ + h) * 8) + s) * HD_;
        #pragma unroll
        for (int dd = 0; dd < HD_; dd += 4) {
            float4 v = *(const float4*)(Qp + dd);
            qr[dd+0] = v.x; qr[dd+1] = v.y; qr[dd+2] = v.z; qr[dd+3] = v.w;
        }
    }

    const float* Kt = Ks + (lql * NH_ + h) * 8 * HD_;
    const float* Vt = Vs + (lql * NH_ + h) * 8 * HD_;

    float logit[8];
    float mx = -1e30f;
    #pragma unroll
    for (int j = 0; j < 8; j++) {
        float acc = 0.f;
        const float* kp = Kt + j * HD_;
        #pragma unroll
        for (int d = 0; d < HD_; d++) acc = fmaf(qr[d], kp[d], acc);
        logit[j] = acc * scale;
        mx = fmaxf(mx, logit[j]);
    }
    float sum = 0.f;
    #pragma unroll
    for (int j = 0; j < 8; j++) { logit[j] = __expf(logit[j] - mx); sum += logit[j]; }
    float inv = 1.f / sum;

    float accv[HD_];
    #pragma unroll
    for (int d = 0; d < HD_; d++) accv[d] = 0.f;
    #pragma unroll
    for (int j = 0; j < 8; j++) {
        float p = logit[j] * inv;
        const float* vp = Vt + j * HD_;
        #pragma unroll
        for (int d = 0; d < HD_; d++) accv[d] = fmaf(p, vp[d], accv[d]);
    }

    // ctx row layout must match (lq*B + b): here b == s (token axis)
    float* o = g_ctx + ((size_t)(lq * B_ + s)) * D_ + h * HD_;
    #pragma unroll
    for (int d = 0; d < HD_; d += 4)
        *(float4*)(o + d) = make_float4(accv[d], accv[d+1], accv[d+2], accv[d+3]);
}

// ---------------- LayerNorm with fused residual: out = LN(x1 + x2) ----------------
__global__ void __launch_bounds__(256)
ln_kernel(const float* __restrict__ x1, const float* __restrict__ x2,
          const float* __restrict__ gam, const float* __restrict__ bet,
          float* __restrict__ out)
{
    int gwarp = (blockIdx.x * blockDim.x + threadIdx.x) >> 5;
    int lane  = threadIdx.x & 31;
    if (gwarp >= ROWS_) return;
    size_t base = (size_t)gwarp * D_ + lane * 8;

    float v[8];
    {
        float4 a0 = *(const float4*)(x1 + base);
        float4 a1 = *(const float4*)(x1 + base + 4);
        float4 b0 = *(const float4*)(x2 + base);
        float4 b1 = *(const float4*)(x2 + base + 4);
        v[0]=a0.x+b0.x; v[1]=a0.y+b0.y; v[2]=a0.z+b0.z; v[3]=a0.w+b0.w;
        v[4]=a1.x+b1.x; v[5]=a1.y+b1.y; v[6]=a1.z+b1.z; v[7]=a1.w+b1.w;
    }
    float s = 0.f, ss = 0.f;
    #pragma unroll
    for (int j = 0; j < 8; j++) { s += v[j]; ss += v[j]*v[j]; }
    #pragma unroll
    for (int o = 16; o > 0; o >>= 1) {
        s  += __shfl_xor_sync(0xffffffffu, s,  o);
        ss += __shfl_xor_sync(0xffffffffu, ss, o);
    }
    float mean = s * (1.f/256.f);
    float var  = ss * (1.f/256.f) - mean*mean;
    float rstd = rsqrtf(var + 1e-5f);

    int c = lane * 8;
    float4 g0 = *(const float4*)(gam + c);
    float4 g1 = *(const float4*)(gam + c + 4);
    float4 e0 = *(const float4*)(bet + c);
    float4 e1 = *(const float4*)(bet + c + 4);
    float4 o0, o1;
    o0.x = (v[0]-mean)*rstd*g0.x + e0.x;
    o0.y = (v[1]-mean)*rstd*g0.y + e0.y;
    o0.z = (v[2]-mean)*rstd*g0.z + e0.z;
    o0.w = (v[3]-mean)*rstd*g0.w + e0.w;
    o1.x = (v[4]-mean)*rstd*g1.x + e1.x;
    o1.y = (v[5]-mean)*rstd*g1.y + e1.y;
    o1.z = (v[6]-mean)*rstd*g1.z + e1.z;
    o1.w = (v[7]-mean)*rstd*g1.w + e1.w;
    *(float4*)(out + base)     = o0;
    *(float4*)(out + base + 4) = o1;
}

// ---------------- MS-deformable sampling: one warp per (row, head), lane = channel ---
__device__ __forceinline__ float ms_sample(const float* __restrict__ vb,
                                           int y, int x, int H, int W, int lane)
{
    if (x < 0 || x >= W || y < 0 || y >= H) return 0.f;
    return vb[((size_t)(y * W + x)) * HD_ + lane];
}

__global__ void __launch_bounds__(256)
msdeform_kernel()
{
    int gw = (blockIdx.x * blockDim.x + threadIdx.x) >> 5;
    int lane = threadIdx.x & 31;
    if (gw >= ROWS_ * NH_) return;
    int i = gw >> 3, h = gw & 7;
    int s = i >> 3, b = i & 7;   // i = lq*B + b ; s = lq

    float rx = ((s % 60) + 0.5f) * (1.f/60.f);
    float ry = ((s / 60) + 0.5f) * (1.f/60.f);

    // softmax over 12 attention-weight logits
    const float* awp = g_aw + (size_t)i * 96 + h * 12;
    float wgt[12]; float mx = -1e30f;
    #pragma unroll
    for (int t = 0; t < 12; t++) { wgt[t] = awp[t]; mx = fmaxf(mx, wgt[t]); }
    float sm = 0.f;
    #pragma unroll
    for (int t = 0; t < 12; t++) { wgt[t] = __expf(wgt[t] - mx); sm += wgt[t]; }
    float inv = 1.f / sm;

    const float* offp = g_off + (size_t)i * 192 + h * 24;
    const int Hs[3] = {60, 30, 15};
    const int St[3] = {0, 3600, 4500};

    float acc = 0.f;
    #pragma unroll
    for (int l = 0; l < 3; l++) {
        int Hl = Hs[l], Wl = Hs[l];
        const float* vb = g_val + (((size_t)(b*NH_ + h)) * LIN_ + St[l]) * HD_;
        #pragma unroll
        for (int p = 0; p < 4; p++) {
            float ox = offp[l*8 + p*2 + 0];
            float oy = offp[l*8 + p*2 + 1];
            float x = (rx + ox / (float)Wl) * (float)Wl - 0.5f;
            float y = (ry + oy / (float)Hl) * (float)Hl - 0.5f;
            float fx0 = floorf(x), fy0 = floorf(y);
            float fx = x - fx0, fy = y - fy0;
            int x0 = (int)fx0, y0 = (int)fy0;
            float a = wgt[l*4 + p] * inv;
            float s00 = ms_sample(vb, y0,   x0,   Hl, Wl, lane);
            float s01 = ms_sample(vb, y0,   x0+1, Hl, Wl, lane);
            float s10 = ms_sample(vb, y0+1, x0,   Hl, Wl, lane);
            float s11 = ms_sample(vb, y0+1, x0+1, Hl, Wl, lane);
            float bil = s00*(1.f-fx)*(1.f-fy) + s01*fx*(1.f-fy)
                      + s10*(1.f-fx)*fy       + s11*fx*fy;
            acc = fmaf(a, bil, acc);
        }
    }
    g_ms[(size_t)i * D_ + h * HD_ + lane] = acc;
}

// ---------------- host orchestration ----------------
extern "C" void kernel_launch(void* const* d_in, const int* in_sizes, int n_in,
                              void* d_out, int out_size)
{
    (void)in_sizes; (void)n_in; (void)out_size;
    const float* tgt  = (const float*)d_in[0];
    const float* qp   = (const float*)d_in[1];
    const float* src  = (const float*)d_in[2];
    const float* in_w = (const float*)d_in[5];
    const float* in_b = (const float*)d_in[6];
    const float* ow   = (const float*)d_in[7];
    const float* ob   = (const float*)d_in[8];
    const float* sow  = (const float*)d_in[9];
    const float* sob  = (const float*)d_in[10];
    const float* aww  = (const float*)d_in[11];
    const float* awb  = (const float*)d_in[12];
    const float* vw   = (const float*)d_in[13];
    const float* vb   = (const float*)d_in[14];
    const float* cow  = (const float*)d_in[15];
    const float* cob  = (const float*)d_in[16];
    const float* ln1g = (const float*)d_in[17];
    const float* ln1b = (const float*)d_in[18];
    const float* ln2g = (const float*)d_in[19];
    const float* ln2b = (const float*)d_in[20];
    const float* ln3g = (const float*)d_in[21];
    const float* ln3b = (const float*)d_in[22];
    const float* f1w  = (const float*)d_in[23];
    const float* f1b  = (const float*)d_in[24];
    const float* f2w  = (const float*)d_in[25];
    const float* f2b  = (const float*)d_in[26];
    float* out = (float*)d_out;

    float *ctxp, *tp, *tmpp, *offp, *awp, *msp, *tqp, *ffnp;
    cudaGetSymbolAddress((void**)&ctxp, g_ctx);
    cudaGetSymbolAddress((void**)&tp,   g_t);
    cudaGetSymbolAddress((void**)&tmpp, g_tmp);
    cudaGetSymbolAddress((void**)&offp, g_off);
    cudaGetSymbolAddress((void**)&awp,  g_aw);
    cudaGetSymbolAddress((void**)&msp,  g_ms);
    cudaGetSymbolAddress((void**)&tqp,  g_tq);
    cudaGetSymbolAddress((void**)&ffnp, g_ffn);

    const int MT = (ROWS_ + TBM - 1) / TBM;        // 450
    const int VMT = (VROWS_ + TBM - 1) / TBM;      // 591

    // 1) self-attention QKV projection (query_pos folded into Q/K column bias)
    colbias_kernel<<<(768+127)/128, 128>>>(in_w, in_b, qp, 512, 768, 256);
    gemm_nt<2><<<dim3(MT, 12), 256>>>(tgt, in_w, nullptr, ROWS_, 768, 256);

    // 2) attention over the 8-token axis
    attn_kernel<<<LQ_ / ALQ, 128>>>();

    // 3) out projection + ln2
    colbias_kernel<<<2, 128>>>(ow, ob, qp, 0, 256, 256);
    gemm_nt<0><<<dim3(MT, 4), 256>>>(ctxp, ow, tmpp, ROWS_, 256, 256);
    ln_kernel<<<ROWS_/8, 256>>>(tgt, tmpp, ln2g, ln2b, tp);

    // 4) deformable attention: value projection, offsets, weights
    colbias_kernel<<<2, 128>>>(vw, vb, qp, 0, 256, 256);
    gemm_nt<3><<<dim3(VMT, 4), 256>>>(src, vw, nullptr, VROWS_, 256, 256);
    colbias_kernel<<<2, 128>>>(sow, sob, qp, 192, 192, 256);
    gemm_nt<0><<<dim3(MT, 3), 256>>>(tp, sow, offp, ROWS_, 192, 256);
    colbias_kernel<<<1, 128>>>(aww, awb, qp, 96, 96, 256);
    gemm_nt<0><<<dim3(MT, 2), 256>>>(tp, aww, awp, ROWS_, 96, 256);

    // 5) sampling + cross out projection + ln1
    msdeform_kernel<<<ROWS_, 256>>>();
    colbias_kernel<<<2, 128>>>(cow, cob, qp, 0, 256, 256);
    gemm_nt<0><<<dim3(MT, 4), 256>>>(msp, cow, tmpp, ROWS_, 256, 256);
    ln_kernel<<<ROWS_/8, 256>>>(tp, tmpp, ln1g, ln1b, tqp);

    // 6) FFN + ln3 (final output)
    colbias_kernel<<<8, 128>>>(f1w, f1b, qp, 0, 1024, 256);
    gemm_nt<1><<<dim3(MT, 16), 256>>>(tqp, f1w, ffnp, ROWS_, 1024, 256);
    colbias_kernel<<<2, 128>>>(f2w, f2b, qp, 0, 256, 1024);
    gemm_nt<0><<<dim3(MT, 4), 256>>>(ffnp, f2w, tmpp, ROWS_, 256, 1024);
    ln_kernel<<<ROWS_/8, 256>>>(tqp, tmpp, ln3g, ln3b, out);
}

// round 5
// speedup vs baseline: 2.0652x; 2.0652x over previous
#include <cuda_runtime.h>
#include <cuda_bf16.h>
#include <stdint.h>
#include <math.h>

// ---------------- problem constants ----------------
#define D_    256
#define NH_   8
#define HD_   32
#define B_    8
#define LQ_   3600
#define LIN_  4725
#define ROWS_ (LQ_*B_)       // 28800
#define VROWS_ (B_*LIN_)     // 37800
#define DFF_  1024

// ---------------- bf16 hi/lo arenas ----------------
#define SZ_TGT (ROWS_*D_)
#define SZ_SRC (VROWS_*D_)
#define SZ_RC  (ROWS_*D_)
#define SZ_FFN (ROWS_*DFF_)
#define OFF_TGT 0
#define OFF_SRC (OFF_TGT+SZ_TGT)
#define OFF_CTX (OFF_SRC+SZ_SRC)
#define OFF_T   (OFF_CTX+SZ_RC)
#define OFF_MS  (OFF_T+SZ_RC)
#define OFF_TQ  (OFF_MS+SZ_RC)
#define OFF_FFN (OFF_TQ+SZ_RC)
#define ARENA_SZ (OFF_FFN+SZ_FFN)

__device__ __align__(256) __nv_bfloat16 g_hi[ARENA_SZ];
__device__ __align__(256) __nv_bfloat16 g_lo[ARENA_SZ];

// weight arena
#define WOFF_IN  0
#define WOFF_OW  (WOFF_IN+768*256)
#define WOFF_VW  (WOFF_OW+256*256)
#define WOFF_SOW (WOFF_VW+256*256)
#define WOFF_AWW (WOFF_SOW+192*256)
#define WOFF_COW (WOFF_AWW+96*256)
#define WOFF_F1  (WOFF_COW+256*256)
#define WOFF_F2  (WOFF_F1+1024*256)
#define WARENA   (WOFF_F2+256*1024)
__device__ __align__(256) __nv_bfloat16 g_whi[WARENA];
__device__ __align__(256) __nv_bfloat16 g_wlo[WARENA];

// fp32 scratch
__device__ __align__(256) float g_Q  [(size_t)LQ_*NH_*8*HD_];
__device__ __align__(256) float g_K  [(size_t)LQ_*NH_*8*HD_];
__device__ __align__(256) float g_Vv [(size_t)LQ_*NH_*8*HD_];
__device__ __align__(256) float g_t  [(size_t)ROWS_*D_];
__device__ __align__(256) float g_tmp[(size_t)ROWS_*D_];
__device__ __align__(256) float g_tq [(size_t)ROWS_*D_];
__device__ __align__(256) float g_val[(size_t)B_*NH_*LIN_*HD_];
__device__ __align__(256) float g_off[(size_t)ROWS_*192];
__device__ __align__(256) float g_aw [(size_t)ROWS_*96];
__device__ __align__(256) float g_cball[8*1024];

// ---------------- helpers ----------------
__device__ __forceinline__ uint32_t smem_u32(const void* p){
    uint32_t a;
    asm("{ .reg .u64 t; cvta.to.shared.u64 t, %1; cvt.u32.u64 %0, t; }" : "=r"(a) : "l"(p));
    return a;
}
__device__ __forceinline__ void splitf(float v, unsigned short& h, unsigned short& l){
    __nv_bfloat16 hb = __float2bfloat16_rn(v);
    float r = v - __bfloat162float(hb);
    __nv_bfloat16 lb = __float2bfloat16_rn(r);
    h = __bfloat16_as_ushort(hb);
    l = __bfloat16_as_ushort(lb);
}

#define LDSM4(r, addr) \
    asm volatile("ldmatrix.sync.aligned.m8n8.x4.shared.b16 {%0,%1,%2,%3}, [%4];" \
        : "=r"((r)[0]), "=r"((r)[1]), "=r"((r)[2]), "=r"((r)[3]) : "r"(addr))

#define MMA16816(d, a, b) \
    asm volatile("mma.sync.aligned.m16n8k16.row.col.f32.bf16.bf16.f32 " \
        "{%0,%1,%2,%3}, {%4,%5,%6,%7}, {%8,%9}, {%0,%1,%2,%3};" \
        : "+f"((d)[0]), "+f"((d)[1]), "+f"((d)[2]), "+f"((d)[3]) \
        : "r"((a)[0]), "r"((a)[1]), "r"((a)[2]), "r"((a)[3]), "r"((b)[0]), "r"((b)[1]))

#define CPA16(sa, ga) asm volatile("cp.async.cg.shared.global [%0], [%1], 16;" :: "r"(sa), "l"(ga))
#define CPA_COMMIT()  asm volatile("cp.async.commit_group;")

// ---------------- setup: all 8 column-bias vectors in one launch ----------------
struct CbArgs { const float* W[8]; const float* Bv[8]; int N[8]; int K[8]; int lim[8]; };
__global__ void cb_kernel(CbArgs a, const float* __restrict__ qp)
{
    int g = blockIdx.x * 128 + threadIdx.x;
    int seg = g >> 10, n = g & 1023;
    if (n >= a.N[seg]) return;
    float v = a.Bv[seg][n];
    if (n < a.lim[seg]) {
        const float* w = a.W[seg] + (size_t)n * a.K[seg];
        float acc = 0.f;
        for (int k = 0; k < a.K[seg]; k += 4) {
            float4 wv = *(const float4*)(w + k);
            float4 qv = *(const float4*)(qp + k);
            acc += wv.x*qv.x + wv.y*qv.y + wv.z*qv.z + wv.w*qv.w;
        }
        v += acc;
    }
    g_cball[seg*1024 + n] = v;
}

// ---------------- weight fp32 -> bf16 hi/lo ----------------
struct WArgs { const float* p[8]; };
__global__ void cvtw_kernel(WArgs a)
{
    int e = (blockIdx.x * 256 + threadIdx.x) * 4;
    if (e >= WARENA) return;
    const int offs[9] = {0,196608,262144,327680,376832,401408,466944,729088,991232};
    int seg = 0;
    #pragma unroll
    for (int s = 1; s < 8; s++) if (e >= offs[s]) seg = s;
    float4 v = *(const float4*)(a.p[seg] + (e - offs[seg]));
    unsigned short h0,h1,h2,h3,l0,l1,l2,l3;
    splitf(v.x,h0,l0); splitf(v.y,h1,l1); splitf(v.z,h2,l2); splitf(v.w,h3,l3);
    *(uint2*)(g_whi+e) = make_uint2((uint32_t)h0 | ((uint32_t)h1<<16), (uint32_t)h2 | ((uint32_t)h3<<16));
    *(uint2*)(g_wlo+e) = make_uint2((uint32_t)l0 | ((uint32_t)l1<<16), (uint32_t)l2 | ((uint32_t)l3<<16));
}

// ---------------- activation inputs (tgt, src) -> bf16 hi/lo ----------------
__global__ void cvta_kernel(const float* __restrict__ tgt, const float* __restrict__ src)
{
    int e = (blockIdx.x * 256 + threadIdx.x) * 4;
    if (e >= SZ_TGT + SZ_SRC) return;
    const float* sp; int dst;
    if (e < SZ_TGT) { sp = tgt + e; dst = OFF_TGT + e; }
    else            { sp = src + (e - SZ_TGT); dst = OFF_SRC + (e - SZ_TGT); }
    float4 v = *(const float4*)sp;
    unsigned short h0,h1,h2,h3,l0,l1,l2,l3;
    splitf(v.x,h0,l0); splitf(v.y,h1,l1); splitf(v.z,h2,l2); splitf(v.w,h3,l3);
    *(uint2*)(g_hi+dst) = make_uint2((uint32_t)h0 | ((uint32_t)h1<<16), (uint32_t)h2 | ((uint32_t)h3<<16));
    *(uint2*)(g_lo+dst) = make_uint2((uint32_t)l0 | ((uint32_t)l1<<16), (uint32_t)l2 | ((uint32_t)l3<<16));
}

// ---------------- mma.sync GEMM: C[m,n] = A[m,:]·W[n,:] + cb[n] ----------------
// 128x128 tile, 8 warps (2M x 4N), warp tile 64x32, BK=32, double-buffered cp.async.
// 3-term bf16 split: AhWh + AhWl + AlWh, fp32 accum.
// Stage layout (80B rows): Ah@0 Al@10240 Wh@20480 Wl@30720, stage stride 40960.
// MODE 0: fp32 store   MODE 1: relu -> bf16 hi/lo   MODE 2: QKV scatter   MODE 3: value scatter
#define GSMEM (2*40960 + 512)

template<int MODE>
__global__ void __launch_bounds__(256)
gemm_mma(const __nv_bfloat16* __restrict__ Ahi, const __nv_bfloat16* __restrict__ Alo,
         const __nv_bfloat16* __restrict__ Whi, const __nv_bfloat16* __restrict__ Wlo,
         float* __restrict__ C, __nv_bfloat16* __restrict__ Chi, __nv_bfloat16* __restrict__ Clo,
         const float* __restrict__ cb, int M, int N, int K)
{
    extern __shared__ __align__(16) char smc[];
    uint32_t sb = smem_u32(smc);
    float* biass = (float*)(smc + 81920);
    int tid = threadIdx.x, wid = tid >> 5, lane = tid & 31;
    int m0 = blockIdx.x * 128, n0 = blockIdx.y * 128;

    if (tid < 128) biass[tid] = cb[n0 + tid];

    float acc[4][4][4];
    #pragma unroll
    for (int i = 0; i < 4; i++)
        #pragma unroll
        for (int j = 0; j < 4; j++)
            #pragma unroll
            for (int e = 0; e < 4; e++) acc[i][j][e] = 0.f;

    const int NC = K >> 5;
    const int wm = (wid & 1) * 64, wn = (wid >> 1) * 32;

    auto stage_load = [&](int c, int st) {
        size_t kb = (size_t)c * 32;
        uint32_t base = sb + st * 40960;
        #pragma unroll
        for (int i = 0; i < 8; i++) {
            int chunk = tid + i * 256;
            int mat = chunk >> 9;
            int idx = chunk & 511;
            int row = idx >> 2, cc = idx & 3;
            uint32_t sa = base + mat*10240 + row*80 + cc*16;
            const __nv_bfloat16* gp;
            bool valid;
            if (mat < 2) {
                int gm = m0 + row; valid = gm < M;
                gp = (mat ? Alo : Ahi) + ((size_t)(valid ? gm : 0) * K + kb + cc*8);
            } else {
                int gn = n0 + row; valid = gn < N;
                gp = (mat == 3 ? Wlo : Whi) + ((size_t)(valid ? gn : 0) * K + kb + cc*8);
            }
            if (valid) CPA16(sa, gp);
            else       asm volatile("st.shared.v4.b32 [%0], {%1,%1,%1,%1};" :: "r"(sa), "r"(0u));
        }
        CPA_COMMIT();
    };

    stage_load(0, 0);

    for (int c = 0; c < NC; c++) {
        int st = c & 1;
        if (c + 1 < NC) {
            stage_load(c + 1, st ^ 1);
            asm volatile("cp.async.wait_group 1;");
        } else {
            asm volatile("cp.async.wait_group 0;");
        }
        __syncthreads();

        uint32_t ab = sb + st * 40960;
        int g = lane >> 3, li = lane & 7;
        #pragma unroll
        for (int k16 = 0; k16 < 2; k16++) {
            uint32_t aH[4][4], aL[4][4], bH[4][2], bL[4][2];
            #pragma unroll
            for (int mt = 0; mt < 4; mt++) {
                int row = wm + mt*16 + (g & 1)*8 + li;
                uint32_t ad = ab + row*80 + k16*32 + (g >> 1)*16;
                LDSM4(aH[mt], ad);
                LDSM4(aL[mt], ad + 10240);
            }
            #pragma unroll
            for (int np = 0; np < 2; np++) {
                int row = wn + np*16 + ((lane >= 16) ? 8 : 0) + li;
                uint32_t bd = ab + 20480 + row*80 + k16*32 + ((lane >> 3) & 1)*16;
                uint32_t t4[4];
                LDSM4(t4, bd);
                bH[np*2][0] = t4[0]; bH[np*2][1] = t4[1];
                bH[np*2+1][0] = t4[2]; bH[np*2+1][1] = t4[3];
                LDSM4(t4, bd + 10240);
                bL[np*2][0] = t4[0]; bL[np*2][1] = t4[1];
                bL[np*2+1][0] = t4[2]; bL[np*2+1][1] = t4[3];
            }
            #pragma unroll
            for (int mt = 0; mt < 4; mt++)
                #pragma unroll
                for (int nt = 0; nt < 4; nt++) {
                    MMA16816(acc[mt][nt], aH[mt], bH[nt]);
                    MMA16816(acc[mt][nt], aH[mt], bL[nt]);
                    MMA16816(acc[mt][nt], aL[mt], bH[nt]);
                }
        }
        __syncthreads();
    }

    // ---------------- epilogue ----------------
    int qr = lane >> 2, qc = (lane & 3) * 2;
    #pragma unroll
    for (int mt = 0; mt < 4; mt++) {
        #pragma unroll
        for (int half = 0; half < 2; half++) {
            int m = m0 + wm + mt*16 + half*8 + qr;
            if (m >= M) continue;
            #pragma unroll
            for (int nt = 0; nt < 4; nt++) {
                int cl = wn + nt*8 + qc;
                int n = n0 + cl;
                if (n >= N) continue;
                float v0 = acc[mt][nt][half*2 + 0] + biass[cl];
                float v1 = acc[mt][nt][half*2 + 1] + biass[cl + 1];
                if (MODE == 0) {
                    *(float2*)(C + (size_t)m * N + n) = make_float2(v0, v1);
                } else if (MODE == 1) {
                    v0 = fmaxf(v0, 0.f); v1 = fmaxf(v1, 0.f);
                    unsigned short h0,h1,l0,l1;
                    splitf(v0,h0,l0); splitf(v1,h1,l1);
                    size_t o = (size_t)m * N + n;
                    *(uint32_t*)(Chi + o) = (uint32_t)h0 | ((uint32_t)h1 << 16);
                    *(uint32_t*)(Clo + o) = (uint32_t)l0 | ((uint32_t)l1 << 16);
                } else if (MODE == 2) {
                    int lq = m >> 3, b = m & 7;
                    int part = n >> 8, h = (n >> 5) & 7, d = n & 31;
                    size_t o = ((((size_t)lq * NH_ + h) * 8) + b) * HD_ + d;
                    float* dstb = (part == 0) ? g_Q : (part == 1) ? g_K : g_Vv;
                    *(float2*)(dstb + o) = make_float2(v0, v1);
                } else {
                    int b = m / LIN_, lin = m - b * LIN_;
                    int h = n >> 5, d = n & 31;
                    size_t o = (((size_t)(b*NH_ + h)) * LIN_ + lin) * HD_ + d;
                    *(float2*)(g_val + o) = make_float2(v0, v1);
                }
            }
        }
    }
}

// ---------------- self-attention over the 8-token axis (writes ctx hi/lo) ----------------
#define ALQ 2
__global__ void __launch_bounds__(128)
attn_kernel()
{
    __shared__ float Ks[ALQ * NH_ * 8 * HD_];
    __shared__ float Vs[ALQ * NH_ * 8 * HD_];

    int lq0 = blockIdx.x * ALQ;
    int t = threadIdx.x;

    const float4* kg = (const float4*)(g_K  + (size_t)lq0 * NH_ * 8 * HD_);
    const float4* vg = (const float4*)(g_Vv + (size_t)lq0 * NH_ * 8 * HD_);
    #pragma unroll
    for (int f = 0; f < ALQ * NH_ * 8 * HD_ / 4 / 128; f++) {
        int idx = f * 128 + t;
        ((float4*)Ks)[idx] = kg[idx];
        ((float4*)Vs)[idx] = vg[idx];
    }
    __syncthreads();

    int lql = t >> 6;
    int r   = t & 63;
    int h   = r >> 3;
    int s   = r & 7;
    int lq  = lq0 + lql;

    const float scale = 0.17677669529663687f;
    float qr[HD_];
    {
        const float* Qp = g_Q + ((((size_t)lq * NH_ + h) * 8) + s) * HD_;
        #pragma unroll
        for (int dd = 0; dd < HD_; dd += 4) {
            float4 v = *(const float4*)(Qp + dd);
            qr[dd+0] = v.x; qr[dd+1] = v.y; qr[dd+2] = v.z; qr[dd+3] = v.w;
        }
    }

    const float* Kt = Ks + (lql * NH_ + h) * 8 * HD_;
    const float* Vt = Vs + (lql * NH_ + h) * 8 * HD_;

    float logit[8];
    float mx = -1e30f;
    #pragma unroll
    for (int j = 0; j < 8; j++) {
        float acc = 0.f;
        const float* kp = Kt + j * HD_;
        #pragma unroll
        for (int d = 0; d < HD_; d++) acc = fmaf(qr[d], kp[d], acc);
        logit[j] = acc * scale;
        mx = fmaxf(mx, logit[j]);
    }
    float sum = 0.f;
    #pragma unroll
    for (int j = 0; j < 8; j++) { logit[j] = __expf(logit[j] - mx); sum += logit[j]; }
    float inv = 1.f / sum;

    float accv[HD_];
    #pragma unroll
    for (int d = 0; d < HD_; d++) accv[d] = 0.f;
    #pragma unroll
    for (int j = 0; j < 8; j++) {
        float p = logit[j] * inv;
        const float* vp = Vt + j * HD_;
        #pragma unroll
        for (int d = 0; d < HD_; d++) accv[d] = fmaf(p, vp[d], accv[d]);
    }

    size_t rowbase = ((size_t)(lq * B_ + s)) * D_ + h * HD_;
    __nv_bfloat16* oh = g_hi + OFF_CTX + rowbase;
    __nv_bfloat16* ol = g_lo + OFF_CTX + rowbase;
    #pragma unroll
    for (int d = 0; d < HD_; d += 2) {
        unsigned short h0,h1,l0,l1;
        splitf(accv[d],   h0, l0);
        splitf(accv[d+1], h1, l1);
        *(uint32_t*)(oh + d) = (uint32_t)h0 | ((uint32_t)h1 << 16);
        *(uint32_t*)(ol + d) = (uint32_t)l0 | ((uint32_t)l1 << 16);
    }
}

// ---------------- LayerNorm(x1 + x2), optional bf16 hi/lo side-output ----------------
__global__ void __launch_bounds__(256)
ln_kernel(const float* __restrict__ x1, const float* __restrict__ x2,
          const float* __restrict__ gam, const float* __restrict__ bet,
          float* __restrict__ out, __nv_bfloat16* __restrict__ ohi, __nv_bfloat16* __restrict__ olo)
{
    int gwarp = (blockIdx.x * blockDim.x + threadIdx.x) >> 5;
    int lane  = threadIdx.x & 31;
    if (gwarp >= ROWS_) return;
    size_t base = (size_t)gwarp * D_ + lane * 8;

    float v[8];
    {
        float4 a0 = *(const float4*)(x1 + base);
        float4 a1 = *(const float4*)(x1 + base + 4);
        float4 b0 = *(const float4*)(x2 + base);
        float4 b1 = *(const float4*)(x2 + base + 4);
        v[0]=a0.x+b0.x; v[1]=a0.y+b0.y; v[2]=a0.z+b0.z; v[3]=a0.w+b0.w;
        v[4]=a1.x+b1.x; v[5]=a1.y+b1.y; v[6]=a1.z+b1.z; v[7]=a1.w+b1.w;
    }
    float s = 0.f, ss = 0.f;
    #pragma unroll
    for (int j = 0; j < 8; j++) { s += v[j]; ss += v[j]*v[j]; }
    #pragma unroll
    for (int o = 16; o > 0; o >>= 1) {
        s  += __shfl_xor_sync(0xffffffffu, s,  o);
        ss += __shfl_xor_sync(0xffffffffu, ss, o);
    }
    float mean = s * (1.f/256.f);
    float var  = ss * (1.f/256.f) - mean*mean;
    float rstd = rsqrtf(var + 1e-5f);

    int c = lane * 8;
    float4 g0 = *(const float4*)(gam + c);
    float4 g1 = *(const float4*)(gam + c + 4);
    float4 e0 = *(const float4*)(bet + c);
    float4 e1 = *(const float4*)(bet + c + 4);
    float ov[8];
    ov[0] = (v[0]-mean)*rstd*g0.x + e0.x;
    ov[1] = (v[1]-mean)*rstd*g0.y + e0.y;
    ov[2] = (v[2]-mean)*rstd*g0.z + e0.z;
    ov[3] = (v[3]-mean)*rstd*g0.w + e0.w;
    ov[4] = (v[4]-mean)*rstd*g1.x + e1.x;
    ov[5] = (v[5]-mean)*rstd*g1.y + e1.y;
    ov[6] = (v[6]-mean)*rstd*g1.z + e1.z;
    ov[7] = (v[7]-mean)*rstd*g1.w + e1.w;
    *(float4*)(out + base)     = make_float4(ov[0], ov[1], ov[2], ov[3]);
    *(float4*)(out + base + 4) = make_float4(ov[4], ov[5], ov[6], ov[7]);

    if (ohi) {
        union { unsigned short us[8]; uint4 u; } ph, pl;
        #pragma unroll
        for (int j = 0; j < 8; j++) splitf(ov[j], ph.us[j], pl.us[j]);
        *(uint4*)(ohi + base) = ph.u;
        *(uint4*)(olo + base) = pl.u;
    }
}

// ---------------- MS-deformable sampling (writes ms hi/lo) ----------------
__device__ __forceinline__ float ms_sample(const float* __restrict__ vb,
                                           int y, int x, int H, int W, int lane)
{
    if (x < 0 || x >= W || y < 0 || y >= H) return 0.f;
    return vb[((size_t)(y * W + x)) * HD_ + lane];
}

__global__ void __launch_bounds__(256)
msdeform_kernel()
{
    int gw = (blockIdx.x * blockDim.x + threadIdx.x) >> 5;
    int lane = threadIdx.x & 31;
    if (gw >= ROWS_ * NH_) return;
    int i = gw >> 3, h = gw & 7;
    int s = i >> 3, b = i & 7;

    float rx = ((s % 60) + 0.5f) * (1.f/60.f);
    float ry = ((s / 60) + 0.5f) * (1.f/60.f);

    const float* awp = g_aw + (size_t)i * 96 + h * 12;
    float wgt[12]; float mx = -1e30f;
    #pragma unroll
    for (int t = 0; t < 12; t++) { wgt[t] = awp[t]; mx = fmaxf(mx, wgt[t]); }
    float sm = 0.f;
    #pragma unroll
    for (int t = 0; t < 12; t++) { wgt[t] = __expf(wgt[t] - mx); sm += wgt[t]; }
    float inv = 1.f / sm;

    const float* offp = g_off + (size_t)i * 192 + h * 24;
    const int Hs[3] = {60, 30, 15};
    const int St[3] = {0, 3600, 4500};

    float acc = 0.f;
    #pragma unroll
    for (int l = 0; l < 3; l++) {
        int Hl = Hs[l], Wl = Hs[l];
        const float* vb = g_val + (((size_t)(b*NH_ + h)) * LIN_ + St[l]) * HD_;
        #pragma unroll
        for (int p = 0; p < 4; p++) {
            float ox = offp[l*8 + p*2 + 0];
            float oy = offp[l*8 + p*2 + 1];
            float x = (rx + ox / (float)Wl) * (float)Wl - 0.5f;
            float y = (ry + oy / (float)Hl) * (float)Hl - 0.5f;
            float fx0 = floorf(x), fy0 = floorf(y);
            float fx = x - fx0, fy = y - fy0;
            int x0 = (int)fx0, y0 = (int)fy0;
            float a = wgt[l*4 + p] * inv;
            float s00 = ms_sample(vb, y0,   x0,   Hl, Wl, lane);
            float s01 = ms_sample(vb, y0,   x0+1, Hl, Wl, lane);
            float s10 = ms_sample(vb, y0+1, x0,   Hl, Wl, lane);
            float s11 = ms_sample(vb, y0+1, x0+1, Hl, Wl, lane);
            float bil = s00*(1.f-fx)*(1.f-fy) + s01*fx*(1.f-fy)
                      + s10*(1.f-fx)*fy       + s11*fx*fy;
            acc = fmaf(a, bil, acc);
        }
    }
    size_t idx = (size_t)i * D_ + h * HD_ + lane;
    unsigned short hh, ll;
    splitf(acc, hh, ll);
    g_hi[OFF_MS + idx] = __ushort_as_bfloat16(hh);
    g_lo[OFF_MS + idx] = __ushort_as_bfloat16(ll);
}

// ---------------- host orchestration ----------------
extern "C" void kernel_launch(void* const* d_in, const int* in_sizes, int n_in,
                              void* d_out, int out_size)
{
    (void)in_sizes; (void)n_in; (void)out_size;
    const float* tgt  = (const float*)d_in[0];
    const float* qp   = (const float*)d_in[1];
    const float* src  = (const float*)d_in[2];
    const float* in_w = (const float*)d_in[5];
    const float* in_b = (const float*)d_in[6];
    const float* ow   = (const float*)d_in[7];
    const float* ob   = (const float*)d_in[8];
    const float* sow  = (const float*)d_in[9];
    const float* sob  = (const float*)d_in[10];
    const float* aww  = (const float*)d_in[11];
    const float* awb  = (const float*)d_in[12];
    const float* vw   = (const float*)d_in[13];
    const float* vb   = (const float*)d_in[14];
    const float* cow  = (const float*)d_in[15];
    const float* cob  = (const float*)d_in[16];
    const float* ln1g = (const float*)d_in[17];
    const float* ln1b = (const float*)d_in[18];
    const float* ln2g = (const float*)d_in[19];
    const float* ln2b = (const float*)d_in[20];
    const float* ln3g = (const float*)d_in[21];
    const float* ln3b = (const float*)d_in[22];
    const float* f1w  = (const float*)d_in[23];
    const float* f1b  = (const float*)d_in[24];
    const float* f2w  = (const float*)d_in[25];
    const float* f2b  = (const float*)d_in[26];
    float* out = (float*)d_out;

    __nv_bfloat16 *hi, *lo, *whi, *wlo;
    float *tp, *tmpp, *tqp, *offp, *awp, *cbp;
    cudaGetSymbolAddress((void**)&hi,  g_hi);
    cudaGetSymbolAddress((void**)&lo,  g_lo);
    cudaGetSymbolAddress((void**)&whi, g_whi);
    cudaGetSymbolAddress((void**)&wlo, g_wlo);
    cudaGetSymbolAddress((void**)&tp,   g_t);
    cudaGetSymbolAddress((void**)&tmpp, g_tmp);
    cudaGetSymbolAddress((void**)&tqp,  g_tq);
    cudaGetSymbolAddress((void**)&offp, g_off);
    cudaGetSymbolAddress((void**)&awp,  g_aw);
    cudaGetSymbolAddress((void**)&cbp,  g_cball);

    cudaFuncSetAttribute(gemm_mma<0>, cudaFuncAttributeMaxDynamicSharedMemorySize, GSMEM);
    cudaFuncSetAttribute(gemm_mma<1>, cudaFuncAttributeMaxDynamicSharedMemorySize, GSMEM);
    cudaFuncSetAttribute(gemm_mma<2>, cudaFuncAttributeMaxDynamicSharedMemorySize, GSMEM);
    cudaFuncSetAttribute(gemm_mma<3>, cudaFuncAttributeMaxDynamicSharedMemorySize, GSMEM);

    // ---- setup ----
    CbArgs ca;
    ca.W[0]=in_w; ca.Bv[0]=in_b; ca.N[0]=768;  ca.K[0]=256;  ca.lim[0]=512;
    ca.W[1]=ow;   ca.Bv[1]=ob;   ca.N[1]=256;  ca.K[1]=256;  ca.lim[1]=0;
    ca.W[2]=vw;   ca.Bv[2]=vb;   ca.N[2]=256;  ca.K[2]=256;  ca.lim[2]=0;
    ca.W[3]=sow;  ca.Bv[3]=sob;  ca.N[3]=192;  ca.K[3]=256;  ca.lim[3]=192;
    ca.W[4]=aww;  ca.Bv[4]=awb;  ca.N[4]=96;   ca.K[4]=256;  ca.lim[4]=96;
    ca.W[5]=cow;  ca.Bv[5]=cob;  ca.N[5]=256;  ca.K[5]=256;  ca.lim[5]=0;
    ca.W[6]=f1w;  ca.Bv[6]=f1b;  ca.N[6]=1024; ca.K[6]=256;  ca.lim[6]=0;
    ca.W[7]=f2w;  ca.Bv[7]=f2b;  ca.N[7]=256;  ca.K[7]=1024; ca.lim[7]=0;
    cb_kernel<<<64, 128>>>(ca, qp);

    WArgs wa;
    wa.p[0]=in_w; wa.p[1]=ow; wa.p[2]=vw; wa.p[3]=sow;
    wa.p[4]=aww;  wa.p[5]=cow; wa.p[6]=f1w; wa.p[7]=f2w;
    cvtw_kernel<<<(WARENA/4 + 255)/256, 256>>>(wa);
    cvta_kernel<<<((SZ_TGT+SZ_SRC)/4 + 255)/256, 256>>>(tgt, src);

    const int MT  = 225;   // 28800/128
    const int VMT = 296;   // ceil(37800/128)

    // 1) QKV projection (qp folded into Q/K bias), scatter
    gemm_mma<2><<<dim3(MT, 6), 256, GSMEM>>>(hi+OFF_TGT, lo+OFF_TGT, whi+WOFF_IN, wlo+WOFF_IN,
                                             nullptr, nullptr, nullptr, cbp+0*1024, ROWS_, 768, 256);
    // 2) tiny self-attention
    attn_kernel<<<LQ_/ALQ, 128>>>();
    // 3) out projection + ln2
    gemm_mma<0><<<dim3(MT, 2), 256, GSMEM>>>(hi+OFF_CTX, lo+OFF_CTX, whi+WOFF_OW, wlo+WOFF_OW,
                                             tmpp, nullptr, nullptr, cbp+1*1024, ROWS_, 256, 256);
    ln_kernel<<<ROWS_/8, 256>>>(tgt, tmpp, ln2g, ln2b, tp, hi+OFF_T, lo+OFF_T);
    // 4) value projection (scatter), offsets, attention weights
    gemm_mma<3><<<dim3(VMT, 2), 256, GSMEM>>>(hi+OFF_SRC, lo+OFF_SRC, whi+WOFF_VW, wlo+WOFF_VW,
                                              nullptr, nullptr, nullptr, cbp+2*1024, VROWS_, 256, 256);
    gemm_mma<0><<<dim3(MT, 2), 256, GSMEM>>>(hi+OFF_T, lo+OFF_T, whi+WOFF_SOW, wlo+WOFF_SOW,
                                             offp, nullptr, nullptr, cbp+3*1024, ROWS_, 192, 256);
    gemm_mma<0><<<dim3(MT, 1), 256, GSMEM>>>(hi+OFF_T, lo+OFF_T, whi+WOFF_AWW, wlo+WOFF_AWW,
                                             awp, nullptr, nullptr, cbp+4*1024, ROWS_, 96, 256);
    // 5) sampling + cross projection + ln1
    msdeform_kernel<<<ROWS_, 256>>>();
    gemm_mma<0><<<dim3(MT, 2), 256, GSMEM>>>(hi+OFF_MS, lo+OFF_MS, whi+WOFF_COW, wlo+WOFF_COW,
                                             tmpp, nullptr, nullptr, cbp+5*1024, ROWS_, 256, 256);
    ln_kernel<<<ROWS_/8, 256>>>(tp, tmpp, ln1g, ln1b, tqp, hi+OFF_TQ, lo+OFF_TQ);
    // 6) FFN + ln3
    gemm_mma<1><<<dim3(MT, 8), 256, GSMEM>>>(hi+OFF_TQ, lo+OFF_TQ, whi+WOFF_F1, wlo+WOFF_F1,
                                             nullptr, hi+OFF_FFN, lo+OFF_FFN, cbp+6*1024, ROWS_, 1024, 256);
    gemm_mma<0><<<dim3(MT, 2), 256, GSMEM>>>(hi+OFF_FFN, lo+OFF_FFN, whi+WOFF_F2, wlo+WOFF_F2,
                                             tmpp, nullptr, nullptr, cbp+7*1024, ROWS_, 256, 1024);
    ln_kernel<<<ROWS_/8, 256>>>(tqp, tmpp, ln3g, ln3b, out, nullptr, nullptr);
}

// round 8
// speedup vs baseline: 2.0754x; 1.0049x over previous
#include <cuda_runtime.h>
#include <cuda_bf16.h>
#include <stdint.h>
#include <math.h>

// ---------------- problem constants ----------------
#define D_    256
#define NH_   8
#define HD_   32
#define B_    8
#define LQ_   3600
#define LIN_  4725
#define ROWS_ (LQ_*B_)       // 28800
#define VROWS_ (B_*LIN_)     // 37800
#define DFF_  1024

// ---------------- bf16 hi/lo arenas ----------------
#define SZ_TGT (ROWS_*D_)
#define SZ_SRC (VROWS_*D_)
#define SZ_RC  (ROWS_*D_)
#define SZ_FFN (ROWS_*DFF_)
#define OFF_TGT 0
#define OFF_SRC (OFF_TGT+SZ_TGT)
#define OFF_CTX (OFF_SRC+SZ_SRC)
#define OFF_T   (OFF_CTX+SZ_RC)
#define OFF_MS  (OFF_T+SZ_RC)
#define OFF_TQ  (OFF_MS+SZ_RC)
#define OFF_FFN (OFF_TQ+SZ_RC)
#define ARENA_SZ (OFF_FFN+SZ_FFN)

__device__ __align__(256) __nv_bfloat16 g_hi[ARENA_SZ];
__device__ __align__(256) __nv_bfloat16 g_lo[ARENA_SZ];

// weight arena (sow and aww adjacent -> mergeable into one N=288 GEMM)
#define WOFF_IN  0
#define WOFF_OW  (WOFF_IN+768*256)
#define WOFF_VW  (WOFF_OW+256*256)
#define WOFF_SOW (WOFF_VW+256*256)
#define WOFF_AWW (WOFF_SOW+192*256)
#define WOFF_COW (WOFF_AWW+96*256)
#define WOFF_F1  (WOFF_COW+256*256)
#define WOFF_F2  (WOFF_F1+1024*256)
#define WARENA   (WOFF_F2+256*1024)
__device__ __align__(256) __nv_bfloat16 g_whi[WARENA];
__device__ __align__(256) __nv_bfloat16 g_wlo[WARENA];

// fp32 scratch
__device__ __align__(256) float g_Q  [(size_t)LQ_*NH_*8*HD_];
__device__ __align__(256) float g_K  [(size_t)LQ_*NH_*8*HD_];
__device__ __align__(256) float g_Vv [(size_t)LQ_*NH_*8*HD_];
__device__ __align__(256) float g_t  [(size_t)ROWS_*D_];
__device__ __align__(256) float g_tmp[(size_t)ROWS_*D_];
__device__ __align__(256) float g_tq [(size_t)ROWS_*D_];
__device__ __align__(256) float g_val[(size_t)B_*NH_*LIN_*HD_];
__device__ __align__(256) float g_off[(size_t)ROWS_*192];
__device__ __align__(256) float g_aw [(size_t)ROWS_*96];
__device__ __align__(256) float g_cball[8*1024];

// ---------------- helpers ----------------
__device__ __forceinline__ uint32_t smem_u32(const void* p){
    uint32_t a;
    asm("{ .reg .u64 t; cvta.to.shared.u64 t, %1; cvt.u32.u64 %0, t; }" : "=r"(a) : "l"(p));
    return a;
}
__device__ __forceinline__ void splitf(float v, unsigned short& h, unsigned short& l){
    __nv_bfloat16 hb = __float2bfloat16_rn(v);
    float r = v - __bfloat162float(hb);
    __nv_bfloat16 lb = __float2bfloat16_rn(r);
    h = __bfloat16_as_ushort(hb);
    l = __bfloat16_as_ushort(lb);
}

#define LDSM4(r, addr) \
    asm volatile("ldmatrix.sync.aligned.m8n8.x4.shared.b16 {%0,%1,%2,%3}, [%4];" \
        : "=r"((r)[0]), "=r"((r)[1]), "=r"((r)[2]), "=r"((r)[3]) : "r"(addr))

#define MMA16816(d, a, b) \
    asm volatile("mma.sync.aligned.m16n8k16.row.col.f32.bf16.bf16.f32 " \
        "{%0,%1,%2,%3}, {%4,%5,%6,%7}, {%8,%9}, {%0,%1,%2,%3};" \
        : "+f"((d)[0]), "+f"((d)[1]), "+f"((d)[2]), "+f"((d)[3]) \
        : "r"((a)[0]), "r"((a)[1]), "r"((a)[2]), "r"((a)[3]), "r"((b)[0]), "r"((b)[1]))

#define CPA16(sa, ga) asm volatile("cp.async.cg.shared.global [%0], [%1], 16;" :: "r"(sa), "l"(ga))
#define CPA_COMMIT()  asm volatile("cp.async.commit_group;")

// ---------------- setup: all 8 column-bias vectors in one launch ----------------
// seg 4 (aww) is packed after seg 3 (sow) so segs 3+4 form one 288-wide bias.
struct CbArgs { const float* W[8]; const float* Bv[8]; int N[8]; int K[8]; int lim[8]; };
__global__ void cb_kernel(CbArgs a, const float* __restrict__ qp)
{
    int g = blockIdx.x * 128 + threadIdx.x;
    int seg = g >> 10, n = g & 1023;
    if (n >= a.N[seg]) return;
    float v = a.Bv[seg][n];
    if (n < a.lim[seg]) {
        const float* w = a.W[seg] + (size_t)n * a.K[seg];
        float acc = 0.f;
        for (int k = 0; k < a.K[seg]; k += 4) {
            float4 wv = *(const float4*)(w + k);
            float4 qv = *(const float4*)(qp + k);
            acc += wv.x*qv.x + wv.y*qv.y + wv.z*qv.z + wv.w*qv.w;
        }
        v += acc;
    }
    int dst = (seg == 4) ? (3*1024 + 192 + n) : (seg*1024 + n);
    g_cball[dst] = v;
}

// ---------------- weight fp32 -> bf16 hi/lo ----------------
struct WArgs { const float* p[8]; };
__global__ void cvtw_kernel(WArgs a)
{
    int e = (blockIdx.x * 256 + threadIdx.x) * 4;
    if (e >= WARENA) return;
    const int offs[9] = {0,196608,262144,327680,376832,401408,466944,729088,991232};
    int seg = 0;
    #pragma unroll
    for (int s = 1; s < 8; s++) if (e >= offs[s]) seg = s;
    float4 v = *(const float4*)(a.p[seg] + (e - offs[seg]));
    unsigned short h0,h1,h2,h3,l0,l1,l2,l3;
    splitf(v.x,h0,l0); splitf(v.y,h1,l1); splitf(v.z,h2,l2); splitf(v.w,h3,l3);
    *(uint2*)(g_whi+e) = make_uint2((uint32_t)h0 | ((uint32_t)h1<<16), (uint32_t)h2 | ((uint32_t)h3<<16));
    *(uint2*)(g_wlo+e) = make_uint2((uint32_t)l0 | ((uint32_t)l1<<16), (uint32_t)l2 | ((uint32_t)l3<<16));
}

// ---------------- activation inputs (tgt, src) -> bf16 hi/lo ----------------
__global__ void cvta_kernel(const float* __restrict__ tgt, const float* __restrict__ src)
{
    int e = (blockIdx.x * 256 + threadIdx.x) * 4;
    if (e >= SZ_TGT + SZ_SRC) return;
    const float* sp; int dst;
    if (e < SZ_TGT) { sp = tgt + e; dst = OFF_TGT + e; }
    else            { sp = src + (e - SZ_TGT); dst = OFF_SRC + (e - SZ_TGT); }
    float4 v = *(const float4*)sp;
    unsigned short h0,h1,h2,h3,l0,l1,l2,l3;
    splitf(v.x,h0,l0); splitf(v.y,h1,l1); splitf(v.z,h2,l2); splitf(v.w,h3,l3);
    *(uint2*)(g_hi+dst) = make_uint2((uint32_t)h0 | ((uint32_t)h1<<16), (uint32_t)h2 | ((uint32_t)h3<<16));
    *(uint2*)(g_lo+dst) = make_uint2((uint32_t)l0 | ((uint32_t)l1<<16), (uint32_t)l2 | ((uint32_t)l3<<16));
}

// ---------------- mma.sync GEMM: C[m,n] = A[m,:]·W[n,:] + cb[n] ----------------
// 128x128 tile, 8 warps (2M x 4N), warp tile 64x32, BK=32, double-buffered cp.async.
// 3-term bf16 split issued TERM-MAJOR (16 independent MMAs per term -> no acc RAW chains).
// MODE 0: fp32 store   MODE 1: relu -> bf16 hi/lo   MODE 2: QKV scatter
// MODE 3: value scatter   MODE 4: off/aw split scatter (N=288 merged GEMM)
#define GSMEM (2*40960 + 512)

template<int MODE>
__global__ void __launch_bounds__(256)
gemm_mma(const __nv_bfloat16* __restrict__ Ahi, const __nv_bfloat16* __restrict__ Alo,
         const __nv_bfloat16* __restrict__ Whi, const __nv_bfloat16* __restrict__ Wlo,
         float* __restrict__ C, __nv_bfloat16* __restrict__ Chi, __nv_bfloat16* __restrict__ Clo,
         const float* __restrict__ cb, int M, int N, int K)
{
    extern __shared__ __align__(16) char smc[];
    uint32_t sb = smem_u32(smc);
    float* biass = (float*)(smc + 81920);
    int tid = threadIdx.x, wid = tid >> 5, lane = tid & 31;
    int m0 = blockIdx.x * 128, n0 = blockIdx.y * 128;

    if (tid < 128) biass[tid] = cb[n0 + tid];

    float acc[4][4][4];
    #pragma unroll
    for (int i = 0; i < 4; i++)
        #pragma unroll
        for (int j = 0; j < 4; j++)
            #pragma unroll
            for (int e = 0; e < 4; e++) acc[i][j][e] = 0.f;

    const int NC = K >> 5;
    const int wm = (wid & 1) * 64, wn = (wid >> 1) * 32;

    auto stage_load = [&](int c, int st) {
        size_t kb = (size_t)c * 32;
        uint32_t base = sb + st * 40960;
        #pragma unroll
        for (int i = 0; i < 8; i++) {
            int chunk = tid + i * 256;
            int mat = chunk >> 9;
            int idx = chunk & 511;
            int row = idx >> 2, cc = idx & 3;
            uint32_t sa = base + mat*10240 + row*80 + cc*16;
            const __nv_bfloat16* gp;
            bool valid;
            if (mat < 2) {
                int gm = m0 + row; valid = gm < M;
                gp = (mat ? Alo : Ahi) + ((size_t)(valid ? gm : 0) * K + kb + cc*8);
            } else {
                int gn = n0 + row; valid = gn < N;
                gp = (mat == 3 ? Wlo : Whi) + ((size_t)(valid ? gn : 0) * K + kb + cc*8);
            }
            if (valid) CPA16(sa, gp);
            else       asm volatile("st.shared.v4.b32 [%0], {%1,%1,%1,%1};" :: "r"(sa), "r"(0u));
        }
        CPA_COMMIT();
    };

    stage_load(0, 0);

    for (int c = 0; c < NC; c++) {
        int st = c & 1;
        if (c + 1 < NC) {
            stage_load(c + 1, st ^ 1);
            asm volatile("cp.async.wait_group 1;");
        } else {
            asm volatile("cp.async.wait_group 0;");
        }
        __syncthreads();

        uint32_t ab = sb + st * 40960;
        int g = lane >> 3, li = lane & 7;
        #pragma unroll
        for (int k16 = 0; k16 < 2; k16++) {
            uint32_t aH[4][4], aL[4][4], bH[4][2], bL[4][2];
            #pragma unroll
            for (int mt = 0; mt < 4; mt++) {
                int row = wm + mt*16 + (g & 1)*8 + li;
                uint32_t ad = ab + row*80 + k16*32 + (g >> 1)*16;
                LDSM4(aH[mt], ad);
                LDSM4(aL[mt], ad + 10240);
            }
            #pragma unroll
            for (int np = 0; np < 2; np++) {
                int row = wn + np*16 + ((lane >= 16) ? 8 : 0) + li;
                uint32_t bd = ab + 20480 + row*80 + k16*32 + ((lane >> 3) & 1)*16;
                uint32_t t4[4];
                LDSM4(t4, bd);
                bH[np*2][0] = t4[0]; bH[np*2][1] = t4[1];
                bH[np*2+1][0] = t4[2]; bH[np*2+1][1] = t4[3];
                LDSM4(t4, bd + 10240);
                bL[np*2][0] = t4[0]; bL[np*2][1] = t4[1];
                bL[np*2+1][0] = t4[2]; bL[np*2+1][1] = t4[3];
            }
            // term-major: 16 independent MMAs per term -> no same-acc RAW chains
            #pragma unroll
            for (int mt = 0; mt < 4; mt++)
                #pragma unroll
                for (int nt = 0; nt < 4; nt++)
                    MMA16816(acc[mt][nt], aH[mt], bH[nt]);
            #pragma unroll
            for (int mt = 0; mt < 4; mt++)
                #pragma unroll
                for (int nt = 0; nt < 4; nt++)
                    MMA16816(acc[mt][nt], aH[mt], bL[nt]);
            #pragma unroll
            for (int mt = 0; mt < 4; mt++)
                #pragma unroll
                for (int nt = 0; nt < 4; nt++)
                    MMA16816(acc[mt][nt], aL[mt], bH[nt]);
        }
        __syncthreads();
    }

    // ---------------- epilogue ----------------
    int qr = lane >> 2, qc = (lane & 3) * 2;
    #pragma unroll
    for (int mt = 0; mt < 4; mt++) {
        #pragma unroll
        for (int half = 0; half < 2; half++) {
            int m = m0 + wm + mt*16 + half*8 + qr;
            if (m >= M) continue;
            #pragma unroll
            for (int nt = 0; nt < 4; nt++) {
                int cl = wn + nt*8 + qc;
                int n = n0 + cl;
                if (n >= N) continue;
                float v0 = acc[mt][nt][half*2 + 0] + biass[cl];
                float v1 = acc[mt][nt][half*2 + 1] + biass[cl + 1];
                if (MODE == 0) {
                    *(float2*)(C + (size_t)m * N + n) = make_float2(v0, v1);
                } else if (MODE == 1) {
                    v0 = fmaxf(v0, 0.f); v1 = fmaxf(v1, 0.f);
                    unsigned short h0,h1,l0,l1;
                    splitf(v0,h0,l0); splitf(v1,h1,l1);
                    size_t o = (size_t)m * N + n;
                    *(uint32_t*)(Chi + o) = (uint32_t)h0 | ((uint32_t)h1 << 16);
                    *(uint32_t*)(Clo + o) = (uint32_t)l0 | ((uint32_t)l1 << 16);
                } else if (MODE == 2) {
                    int lq = m >> 3, b = m & 7;
                    int part = n >> 8, h = (n >> 5) & 7, d = n & 31;
                    size_t o = ((((size_t)lq * NH_ + h) * 8) + b) * HD_ + d;
                    float* dstb = (part == 0) ? g_Q : (part == 1) ? g_K : g_Vv;
                    *(float2*)(dstb + o) = make_float2(v0, v1);
                } else if (MODE == 3) {
                    int b = m / LIN_, lin = m - b * LIN_;
                    int h = n >> 5, d = n & 31;
                    size_t o = (((size_t)(b*NH_ + h)) * LIN_ + lin) * HD_ + d;
                    *(float2*)(g_val + o) = make_float2(v0, v1);
                } else { // MODE 4: cols [0,192) -> g_off, [192,288) -> g_aw
                    if (n < 192)
                        *(float2*)(g_off + (size_t)m * 192 + n) = make_float2(v0, v1);
                    else
                        *(float2*)(g_aw + (size_t)m * 96 + (n - 192)) = make_float2(v0, v1);
                }
            }
        }
    }
}

// ---------------- self-attention over the 8-token axis (writes ctx hi/lo) ----------------
#define ALQ 2
__global__ void __launch_bounds__(128)
attn_kernel()
{
    __shared__ float Ks[ALQ * NH_ * 8 * HD_];
    __shared__ float Vs[ALQ * NH_ * 8 * HD_];

    int lq0 = blockIdx.x * ALQ;
    int t = threadIdx.x;

    const float4* kg = (const float4*)(g_K  + (size_t)lq0 * NH_ * 8 * HD_);
    const float4* vg = (const float4*)(g_Vv + (size_t)lq0 * NH_ * 8 * HD_);
    #pragma unroll
    for (int f = 0; f < ALQ * NH_ * 8 * HD_ / 4 / 128; f++) {
        int idx = f * 128 + t;
        ((float4*)Ks)[idx] = kg[idx];
        ((float4*)Vs)[idx] = vg[idx];
    }
    __syncthreads();

    int lql = t >> 6;
    int r   = t & 63;
    int h   = r >> 3;
    int s   = r & 7;
    int lq  = lq0 + lql;

    const float scale = 0.17677669529663687f;
    float qr[HD_];
    {
        const float* Qp = g_Q + ((((size_t)lq * NH_ + h) * 8) + s) * HD_;
        #pragma unroll
        for (int dd = 0; dd < HD_; dd += 4) {
            float4 v = *(const float4*)(Qp + dd);
            qr[dd+0] = v.x; qr[dd+1] = v.y; qr[dd+2] = v.z; qr[dd+3] = v.w;
        }
    }

    const float* Kt = Ks + (lql * NH_ + h) * 8 * HD_;
    const float* Vt = Vs + (lql * NH_ + h) * 8 * HD_;

    float logit[8];
    float mx = -1e30f;
    #pragma unroll
    for (int j = 0; j < 8; j++) {
        float acc = 0.f;
        const float* kp = Kt + j * HD_;
        #pragma unroll
        for (int d = 0; d < HD_; d++) acc = fmaf(qr[d], kp[d], acc);
        logit[j] = acc * scale;
        mx = fmaxf(mx, logit[j]);
    }
    float sum = 0.f;
    #pragma unroll
    for (int j = 0; j < 8; j++) { logit[j] = __expf(logit[j] - mx); sum += logit[j]; }
    float inv = 1.f / sum;

    float accv[HD_];
    #pragma unroll
    for (int d = 0; d < HD_; d++) accv[d] = 0.f;
    #pragma unroll
    for (int j = 0; j < 8; j++) {
        float p = logit[j] * inv;
        const float* vp = Vt + j * HD_;
        #pragma unroll
        for (int d = 0; d < HD_; d++) accv[d] = fmaf(p, vp[d], accv[d]);
    }

    size_t rowbase = ((size_t)(lq * B_ + s)) * D_ + h * HD_;
    __nv_bfloat16* oh = g_hi + OFF_CTX + rowbase;
    __nv_bfloat16* ol = g_lo + OFF_CTX + rowbase;
    #pragma unroll
    for (int d = 0; d < HD_; d += 2) {
        unsigned short h0,h1,l0,l1;
        splitf(accv[d],   h0, l0);
        splitf(accv[d+1], h1, l1);
        *(uint32_t*)(oh + d) = (uint32_t)h0 | ((uint32_t)h1 << 16);
        *(uint32_t*)(ol + d) = (uint32_t)l0 | ((uint32_t)l1 << 16);
    }
}

// ---------------- LayerNorm(x1 + x2), optional bf16 hi/lo side-output ----------------
__global__ void __launch_bounds__(256)
ln_kernel(const float* __restrict__ x1, const float* __restrict__ x2,
          const float* __restrict__ gam, const float* __restrict__ bet,
          float* __restrict__ out, __nv_bfloat16* __restrict__ ohi, __nv_bfloat16* __restrict__ olo)
{
    int gwarp = (blockIdx.x * blockDim.x + threadIdx.x) >> 5;
    int lane  = threadIdx.x & 31;
    if (gwarp >= ROWS_) return;
    size_t base = (size_t)gwarp * D_ + lane * 8;

    float v[8];
    {
        float4 a0 = *(const float4*)(x1 + base);
        float4 a1 = *(const float4*)(x1 + base + 4);
        float4 b0 = *(const float4*)(x2 + base);
        float4 b1 = *(const float4*)(x2 + base + 4);
        v[0]=a0.x+b0.x; v[1]=a0.y+b0.y; v[2]=a0.z+b0.z; v[3]=a0.w+b0.w;
        v[4]=a1.x+b1.x; v[5]=a1.y+b1.y; v[6]=a1.z+b1.z; v[7]=a1.w+b1.w;
    }
    float s = 0.f, ss = 0.f;
    #pragma unroll
    for (int j = 0; j < 8; j++) { s += v[j]; ss += v[j]*v[j]; }
    #pragma unroll
    for (int o = 16; o > 0; o >>= 1) {
        s  += __shfl_xor_sync(0xffffffffu, s,  o);
        ss += __shfl_xor_sync(0xffffffffu, ss, o);
    }
    float mean = s * (1.f/256.f);
    float var  = ss * (1.f/256.f) - mean*mean;
    float rstd = rsqrtf(var + 1e-5f);

    int c = lane * 8;
    float4 g0 = *(const float4*)(gam + c);
    float4 g1 = *(const float4*)(gam + c + 4);
    float4 e0 = *(const float4*)(bet + c);
    float4 e1 = *(const float4*)(bet + c + 4);
    float ov[8];
    ov[0] = (v[0]-mean)*rstd*g0.x + e0.x;
    ov[1] = (v[1]-mean)*rstd*g0.y + e0.y;
    ov[2] = (v[2]-mean)*rstd*g0.z + e0.z;
    ov[3] = (v[3]-mean)*rstd*g0.w + e0.w;
    ov[4] = (v[4]-mean)*rstd*g1.x + e1.x;
    ov[5] = (v[5]-mean)*rstd*g1.y + e1.y;
    ov[6] = (v[6]-mean)*rstd*g1.z + e1.z;
    ov[7] = (v[7]-mean)*rstd*g1.w + e1.w;
    *(float4*)(out + base)     = make_float4(ov[0], ov[1], ov[2], ov[3]);
    *(float4*)(out + base + 4) = make_float4(ov[4], ov[5], ov[6], ov[7]);

    if (ohi) {
        union { unsigned short us[8]; uint4 u; } ph, pl;
        #pragma unroll
        for (int j = 0; j < 8; j++) splitf(ov[j], ph.us[j], pl.us[j]);
        *(uint4*)(ohi + base) = ph.u;
        *(uint4*)(olo + base) = pl.u;
    }
}

// ---------------- MS-deformable sampling (writes ms hi/lo) ----------------
__device__ __forceinline__ float ms_sample(const float* __restrict__ vb,
                                           int y, int x, int H, int W, int lane)
{
    if (x < 0 || x >= W || y < 0 || y >= H) return 0.f;
    return vb[((size_t)(y * W + x)) * HD_ + lane];
}

__global__ void __launch_bounds__(256)
msdeform_kernel()
{
    int gw = (blockIdx.x * blockDim.x + threadIdx.x) >> 5;
    int lane = threadIdx.x & 31;
    if (gw >= ROWS_ * NH_) return;
    int i = gw >> 3, h = gw & 7;
    int s = i >> 3, b = i & 7;

    float rx = ((s % 60) + 0.5f) * (1.f/60.f);
    float ry = ((s / 60) + 0.5f) * (1.f/60.f);

    const float* awp = g_aw + (size_t)i * 96 + h * 12;
    float wgt[12]; float mx = -1e30f;
    #pragma unroll
    for (int t = 0; t < 12; t++) { wgt[t] = awp[t]; mx = fmaxf(mx, wgt[t]); }
    float sm = 0.f;
    #pragma unroll
    for (int t = 0; t < 12; t++) { wgt[t] = __expf(wgt[t] - mx); sm += wgt[t]; }
    float inv = 1.f / sm;

    const float* offp = g_off + (size_t)i * 192 + h * 24;
    const int Hs[3] = {60, 30, 15};
    const int St[3] = {0, 3600, 4500};

    float acc = 0.f;
    #pragma unroll
    for (int l = 0; l < 3; l++) {
        int Hl = Hs[l], Wl = Hs[l];
        const float* vb = g_val + (((size_t)(b*NH_ + h)) * LIN_ + St[l]) * HD_;
        #pragma unroll
        for (int p = 0; p < 4; p++) {
            float ox = offp[l*8 + p*2 + 0];
            float oy = offp[l*8 + p*2 + 1];
            float x = (rx + ox / (float)Wl) * (float)Wl - 0.5f;
            float y = (ry + oy / (float)Hl) * (float)Hl - 0.5f;
            float fx0 = floorf(x), fy0 = floorf(y);
            float fx = x - fx0, fy = y - fy0;
            int x0 = (int)fx0, y0 = (int)fy0;
            float a = wgt[l*4 + p] * inv;
            float s00 = ms_sample(vb, y0,   x0,   Hl, Wl, lane);
            float s01 = ms_sample(vb, y0,   x0+1, Hl, Wl, lane);
            float s10 = ms_sample(vb, y0+1, x0,   Hl, Wl, lane);
            float s11 = ms_sample(vb, y0+1, x0+1, Hl, Wl, lane);
            float bil = s00*(1.f-fx)*(1.f-fy) + s01*fx*(1.f-fy)
                      + s10*(1.f-fx)*fy       + s11*fx*fy;
            acc = fmaf(a, bil, acc);
        }
    }
    size_t idx = (size_t)i * D_ + h * HD_ + lane;
    unsigned short hh, ll;
    splitf(acc, hh, ll);
    g_hi[OFF_MS + idx] = __ushort_as_bfloat16(hh);
    g_lo[OFF_MS + idx] = __ushort_as_bfloat16(ll);
}

// ---------------- host orchestration ----------------
extern "C" void kernel_launch(void* const* d_in, const int* in_sizes, int n_in,
                              void* d_out, int out_size)
{
    (void)in_sizes; (void)n_in; (void)out_size;
    const float* tgt  = (const float*)d_in[0];
    const float* qp   = (const float*)d_in[1];
    const float* src  = (const float*)d_in[2];
    const float* in_w = (const float*)d_in[5];
    const float* in_b = (const float*)d_in[6];
    const float* ow   = (const float*)d_in[7];
    const float* ob   = (const float*)d_in[8];
    const float* sow  = (const float*)d_in[9];
    const float* sob  = (const float*)d_in[10];
    const float* aww  = (const float*)d_in[11];
    const float* awb  = (const float*)d_in[12];
    const float* vw   = (const float*)d_in[13];
    const float* vb   = (const float*)d_in[14];
    const float* cow  = (const float*)d_in[15];
    const float* cob  = (const float*)d_in[16];
    const float* ln1g = (const float*)d_in[17];
    const float* ln1b = (const float*)d_in[18];
    const float* ln2g = (const float*)d_in[19];
    const float* ln2b = (const float*)d_in[20];
    const float* ln3g = (const float*)d_in[21];
    const float* ln3b = (const float*)d_in[22];
    const float* f1w  = (const float*)d_in[23];
    const float* f1b  = (const float*)d_in[24];
    const float* f2w  = (const float*)d_in[25];
    const float* f2b  = (const float*)d_in[26];
    float* out = (float*)d_out;

    __nv_bfloat16 *hi, *lo, *whi, *wlo;
    float *tp, *tmpp, *tqp, *cbp;
    cudaGetSymbolAddress((void**)&hi,  g_hi);
    cudaGetSymbolAddress((void**)&lo,  g_lo);
    cudaGetSymbolAddress((void**)&whi, g_whi);
    cudaGetSymbolAddress((void**)&wlo, g_wlo);
    cudaGetSymbolAddress((void**)&tp,   g_t);
    cudaGetSymbolAddress((void**)&tmpp, g_tmp);
    cudaGetSymbolAddress((void**)&tqp,  g_tq);
    cudaGetSymbolAddress((void**)&cbp,  g_cball);

    cudaFuncSetAttribute(gemm_mma<0>, cudaFuncAttributeMaxDynamicSharedMemorySize, GSMEM);
    cudaFuncSetAttribute(gemm_mma<1>, cudaFuncAttributeMaxDynamicSharedMemorySize, GSMEM);
    cudaFuncSetAttribute(gemm_mma<2>, cudaFuncAttributeMaxDynamicSharedMemorySize, GSMEM);
    cudaFuncSetAttribute(gemm_mma<3>, cudaFuncAttributeMaxDynamicSharedMemorySize, GSMEM);
    cudaFuncSetAttribute(gemm_mma<4>, cudaFuncAttributeMaxDynamicSharedMemorySize, GSMEM);

    // ---- setup ----
    CbArgs ca;
    ca.W[0]=in_w; ca.Bv[0]=in_b; ca.N[0]=768;  ca.K[0]=256;  ca.lim[0]=512;
    ca.W[1]=ow;   ca.Bv[1]=ob;   ca.N[1]=256;  ca.K[1]=256;  ca.lim[1]=0;
    ca.W[2]=vw;   ca.Bv[2]=vb;   ca.N[2]=256;  ca.K[2]=256;  ca.lim[2]=0;
    ca.W[3]=sow;  ca.Bv[3]=sob;  ca.N[3]=192;  ca.K[3]=256;  ca.lim[3]=192;
    ca.W[4]=aww;  ca.Bv[4]=awb;  ca.N[4]=96;   ca.K[4]=256;  ca.lim[4]=96;
    ca.W[5]=cow;  ca.Bv[5]=cob;  ca.N[5]=256;  ca.K[5]=256;  ca.lim[5]=0;
    ca.W[6]=f1w;  ca.Bv[6]=f1b;  ca.N[6]=1024; ca.K[6]=256;  ca.lim[6]=0;
    ca.W[7]=f2w;  ca.Bv[7]=f2b;  ca.N[7]=256;  ca.K[7]=1024; ca.lim[7]=0;
    cb_kernel<<<64, 128>>>(ca, qp);

    WArgs wa;
    wa.p[0]=in_w; wa.p[1]=ow; wa.p[2]=vw; wa.p[3]=sow;
    wa.p[4]=aww;  wa.p[5]=cow; wa.p[6]=f1w; wa.p[7]=f2w;
    cvtw_kernel<<<(WARENA/4 + 255)/256, 256>>>(wa);
    cvta_kernel<<<((SZ_TGT+SZ_SRC)/4 + 255)/256, 256>>>(tgt, src);

    const int MT  = 225;   // 28800/128
    const int VMT = 296;   // ceil(37800/128)

    // 1) QKV projection (qp folded into Q/K bias), scatter
    gemm_mma<2><<<dim3(MT, 6), 256, GSMEM>>>(hi+OFF_TGT, lo+OFF_TGT, whi+WOFF_IN, wlo+WOFF_IN,
                                             nullptr, nullptr, nullptr, cbp+0*1024, ROWS_, 768, 256);
    // 2) tiny self-attention
    attn_kernel<<<LQ_/ALQ, 128>>>();
    // 3) out projection + ln2
    gemm_mma<0><<<dim3(MT, 2), 256, GSMEM>>>(hi+OFF_CTX, lo+OFF_CTX, whi+WOFF_OW, wlo+WOFF_OW,
                                             tmpp, nullptr, nullptr, cbp+1*1024, ROWS_, 256, 256);
    ln_kernel<<<ROWS_/8, 256>>>(tgt, tmpp, ln2g, ln2b, tp, hi+OFF_T, lo+OFF_T);
    // 4) value projection (scatter) + merged offsets/attention-weights GEMM (N=288)
    gemm_mma<3><<<dim3(VMT, 2), 256, GSMEM>>>(hi+OFF_SRC, lo+OFF_SRC, whi+WOFF_VW, wlo+WOFF_VW,
                                              nullptr, nullptr, nullptr, cbp+2*1024, VROWS_, 256, 256);
    gemm_mma<4><<<dim3(MT, 3), 256, GSMEM>>>(hi+OFF_T, lo+OFF_T, whi+WOFF_SOW, wlo+WOFF_SOW,
                                             nullptr, nullptr, nullptr, cbp+3*1024, ROWS_, 288, 256);
    // 5) sampling + cross projection + ln1
    msdeform_kernel<<<ROWS_, 256>>>();
    gemm_mma<0><<<dim3(MT, 2), 256, GSMEM>>>(hi+OFF_MS, lo+OFF_MS, whi+WOFF_COW, wlo+WOFF_COW,
                                             tmpp, nullptr, nullptr, cbp+5*1024, ROWS_, 256, 256);
    ln_kernel<<<ROWS_/8, 256>>>(tp, tmpp, ln1g, ln1b, tqp, hi+OFF_TQ, lo+OFF_TQ);
    // 6) FFN + ln3
    gemm_mma<1><<<dim3(MT, 8), 256, GSMEM>>>(hi+OFF_TQ, lo+OFF_TQ, whi+WOFF_F1, wlo+WOFF_F1,
                                             nullptr, hi+OFF_FFN, lo+OFF_FFN, cbp+6*1024, ROWS_, 1024, 256);
    gemm_mma<0><<<dim3(MT, 2), 256, GSMEM>>>(hi+OFF_FFN, lo+OFF_FFN, whi+WOFF_F2, wlo+WOFF_F2,
                                             tmpp, nullptr, nullptr, cbp+7*1024, ROWS_, 256, 1024);
    ln_kernel<<<ROWS_/8, 256>>>(tqp, tmpp, ln3g, ln3b, out, nullptr, nullptr);
}

// round 12
// speedup vs baseline: 2.6559x; 1.2797x over previous
#include <cuda_runtime.h>
#include <cuda_fp16.h>
#include <stdint.h>
#include <math.h>

// ---------------- problem constants ----------------
#define D_    256
#define NH_   8
#define HD_   32
#define B_    8
#define LQ_   3600
#define LIN_  4725
#define ROWS_ (LQ_*B_)       // 28800
#define VROWS_ (B_*LIN_)     // 37800
#define DFF_  1024

// ---------------- fp16 activation arena ----------------
#define SZ_TGT (ROWS_*D_)
#define SZ_SRC (VROWS_*D_)
#define SZ_RC  (ROWS_*D_)
#define SZ_FFN (ROWS_*DFF_)
#define OFF_TGT 0
#define OFF_SRC (OFF_TGT+SZ_TGT)
#define OFF_CTX (OFF_SRC+SZ_SRC)
#define OFF_T   (OFF_CTX+SZ_RC)
#define OFF_MS  (OFF_T+SZ_RC)
#define OFF_TQ  (OFF_MS+SZ_RC)
#define OFF_FFN (OFF_TQ+SZ_RC)
#define ARENA_SZ (OFF_FFN+SZ_FFN)

__device__ __align__(256) __half g_act[ARENA_SZ];

// weight arena (fp16 hi/lo; sow and aww adjacent -> merged N=288 GEMM)
#define WOFF_IN  0
#define WOFF_OW  (WOFF_IN+768*256)
#define WOFF_VW  (WOFF_OW+256*256)
#define WOFF_SOW (WOFF_VW+256*256)
#define WOFF_AWW (WOFF_SOW+192*256)
#define WOFF_COW (WOFF_AWW+96*256)
#define WOFF_F1  (WOFF_COW+256*256)
#define WOFF_F2  (WOFF_F1+1024*256)
#define WARENA   (WOFF_F2+256*1024)
__device__ __align__(256) __half g_whi[WARENA];
__device__ __align__(256) __half g_wlo[WARENA];

// scratch
__device__ __align__(256) __half g_Q  [(size_t)LQ_*NH_*8*HD_];
__device__ __align__(256) __half g_K  [(size_t)LQ_*NH_*8*HD_];
__device__ __align__(256) __half g_Vv [(size_t)LQ_*NH_*8*HD_];
__device__ __align__(256) __half g_val[(size_t)B_*NH_*LIN_*HD_];
__device__ __align__(256) float g_t  [(size_t)ROWS_*D_];
__device__ __align__(256) float g_tmp[(size_t)ROWS_*D_];
__device__ __align__(256) float g_tq [(size_t)ROWS_*D_];
__device__ __align__(256) float g_off[(size_t)ROWS_*192];
__device__ __align__(256) float g_aw [(size_t)ROWS_*96];
__device__ __align__(256) float g_cball[8*1024];

// ---------------- helpers ----------------
__device__ __forceinline__ uint32_t smem_u32(const void* p){
    uint32_t a;
    asm("{ .reg .u64 t; cvta.to.shared.u64 t, %1; cvt.u32.u64 %0, t; }" : "=r"(a) : "l"(p));
    return a;
}
__device__ __forceinline__ void splith(float v, __half& h, __half& l){
    h = __float2half_rn(v);
    l = __float2half_rn(v - __half2float(h));
}

#define LDSM4(r, addr) \
    asm volatile("ldmatrix.sync.aligned.m8n8.x4.shared.b16 {%0,%1,%2,%3}, [%4];" \
        : "=r"((r)[0]), "=r"((r)[1]), "=r"((r)[2]), "=r"((r)[3]) : "r"(addr))

#define MMA16816(d, a, b) \
    asm volatile("mma.sync.aligned.m16n8k16.row.col.f32.f16.f16.f32 " \
        "{%0,%1,%2,%3}, {%4,%5,%6,%7}, {%8,%9}, {%0,%1,%2,%3};" \
        : "+f"((d)[0]), "+f"((d)[1]), "+f"((d)[2]), "+f"((d)[3]) \
        : "r"((a)[0]), "r"((a)[1]), "r"((a)[2]), "r"((a)[3]), "r"((b)[0]), "r"((b)[1]))

#define CPA16(sa, ga) asm volatile("cp.async.cg.shared.global [%0], [%1], 16;" :: "r"(sa), "l"(ga))
#define CPA_COMMIT()  asm volatile("cp.async.commit_group;")

// ---------------- setup: all 8 column-bias vectors ----------------
struct CbArgs { const float* W[8]; const float* Bv[8]; int N[8]; int K[8]; int lim[8]; };
__global__ void cb_kernel(CbArgs a, const float* __restrict__ qp)
{
    int g = blockIdx.x * 128 + threadIdx.x;
    int seg = g >> 10, n = g & 1023;
    if (n >= a.N[seg]) return;
    float v = a.Bv[seg][n];
    if (n < a.lim[seg]) {
        const float* w = a.W[seg] + (size_t)n * a.K[seg];
        float acc = 0.f;
        for (int k = 0; k < a.K[seg]; k += 4) {
            float4 wv = *(const float4*)(w + k);
            float4 qv = *(const float4*)(qp + k);
            acc += wv.x*qv.x + wv.y*qv.y + wv.z*qv.z + wv.w*qv.w;
        }
        v += acc;
    }
    int dst = (seg == 4) ? (3*1024 + 192 + n) : (seg*1024 + n);
    g_cball[dst] = v;
}

// ---------------- weight fp32 -> fp16 hi/lo ----------------
struct WArgs { const float* p[8]; };
__global__ void cvtw_kernel(WArgs a)
{
    int e = (blockIdx.x * 256 + threadIdx.x) * 4;
    if (e >= WARENA) return;
    const int offs[9] = {0,196608,262144,327680,376832,401408,466944,729088,991232};
    int seg = 0;
    #pragma unroll
    for (int s = 1; s < 8; s++) if (e >= offs[s]) seg = s;
    float4 v = *(const float4*)(a.p[seg] + (e - offs[seg]));
    __half h0,h1,h2,h3,l0,l1,l2,l3;
    splith(v.x,h0,l0); splith(v.y,h1,l1); splith(v.z,h2,l2); splith(v.w,h3,l3);
    __half2 ph0 = __halves2half2(h0,h1), ph1 = __halves2half2(h2,h3);
    __half2 pl0 = __halves2half2(l0,l1), pl1 = __halves2half2(l2,l3);
    *(uint2*)(g_whi+e) = make_uint2(*(uint32_t*)&ph0, *(uint32_t*)&ph1);
    *(uint2*)(g_wlo+e) = make_uint2(*(uint32_t*)&pl0, *(uint32_t*)&pl1);
}

// ---------------- activation inputs (tgt, src) -> fp16 ----------------
__global__ void cvta_kernel(const float* __restrict__ tgt, const float* __restrict__ src)
{
    int e = (blockIdx.x * 256 + threadIdx.x) * 4;
    if (e >= SZ_TGT + SZ_SRC) return;
    const float* sp; int dst;
    if (e < SZ_TGT) { sp = tgt + e; dst = OFF_TGT + e; }
    else            { sp = src + (e - SZ_TGT); dst = OFF_SRC + (e - SZ_TGT); }
    float4 v = *(const float4*)sp;
    __half2 p0 = __floats2half2_rn(v.x, v.y);
    __half2 p1 = __floats2half2_rn(v.z, v.w);
    *(uint2*)(g_act+dst) = make_uint2(*(uint32_t*)&p0, *(uint32_t*)&p1);
}

// ---------------- mma.sync GEMM: C[m,n] = A[m,:]·W[n,:] + cb[n] ----------------
// fp16 2-term: acc = Ah·Wh + Ah·Wl  (error ≈ Al·W ≈ 2^-12 rel)
// 128x128 tile, 8 warps (2M x 4N), BK=32, double-buffered cp.async.
// Stage (80B rows): Ah@0 Wh@10240 Wl@20480, stage stride 30720.
// MODE 0: fp32   MODE 1: relu->fp16   MODE 2: QKV scatter (fp16)
// MODE 3: value scatter (fp16)   MODE 4: off/aw split scatter (fp32)
#define GSMEM (2*30720 + 512)

template<int MODE>
__global__ void __launch_bounds__(256)
gemm_mma(const __half* __restrict__ A,
         const __half* __restrict__ Whi, const __half* __restrict__ Wlo,
         float* __restrict__ C, __half* __restrict__ Ch,
         const float* __restrict__ cb, int M, int N, int K)
{
    extern __shared__ __align__(16) char smc[];
    uint32_t sb = smem_u32(smc);
    float* biass = (float*)(smc + 61440);
    int tid = threadIdx.x, wid = tid >> 5, lane = tid & 31;
    int m0 = blockIdx.x * 128, n0 = blockIdx.y * 128;

    if (tid < 128) biass[tid] = cb[n0 + tid];

    float acc[4][4][4];
    #pragma unroll
    for (int i = 0; i < 4; i++)
        #pragma unroll
        for (int j = 0; j < 4; j++)
            #pragma unroll
            for (int e = 0; e < 4; e++) acc[i][j][e] = 0.f;

    const int NC = K >> 5;
    const int wm = (wid & 1) * 64, wn = (wid >> 1) * 32;

    auto stage_load = [&](int c, int st) {
        size_t kb = (size_t)c * 32;
        uint32_t base = sb + st * 30720;
        #pragma unroll
        for (int i = 0; i < 6; i++) {
            int chunk = tid + i * 256;
            int mat = chunk >> 9;            // 0=Ah 1=Wh 2=Wl
            int idx = chunk & 511;
            int row = idx >> 2, cc = idx & 3;
            uint32_t sa = base + mat*10240 + row*80 + cc*16;
            const __half* gp;
            bool valid;
            if (mat == 0) {
                int gm = m0 + row; valid = gm < M;
                gp = A + ((size_t)(valid ? gm : 0) * K + kb + cc*8);
            } else {
                int gn = n0 + row; valid = gn < N;
                gp = (mat == 2 ? Wlo : Whi) + ((size_t)(valid ? gn : 0) * K + kb + cc*8);
            }
            if (valid) CPA16(sa, gp);
            else       asm volatile("st.shared.v4.b32 [%0], {%1,%1,%1,%1};" :: "r"(sa), "r"(0u));
        }
        CPA_COMMIT();
    };

    stage_load(0, 0);

    for (int c = 0; c < NC; c++) {
        int st = c & 1;
        if (c + 1 < NC) {
            stage_load(c + 1, st ^ 1);
            asm volatile("cp.async.wait_group 1;");
        } else {
            asm volatile("cp.async.wait_group 0;");
        }
        __syncthreads();

        uint32_t ab = sb + st * 30720;
        int g = lane >> 3, li = lane & 7;
        #pragma unroll
        for (int k16 = 0; k16 < 2; k16++) {
            uint32_t aH[4][4], bH[4][2], bL[4][2];
            #pragma unroll
            for (int mt = 0; mt < 4; mt++) {
                int row = wm + mt*16 + (g & 1)*8 + li;
                uint32_t ad = ab + row*80 + k16*32 + (g >> 1)*16;
                LDSM4(aH[mt], ad);
            }
            #pragma unroll
            for (int np = 0; np < 2; np++) {
                int row = wn + np*16 + ((lane >= 16) ? 8 : 0) + li;
                uint32_t bd = ab + 10240 + row*80 + k16*32 + ((lane >> 3) & 1)*16;
                uint32_t t4[4];
                LDSM4(t4, bd);
                bH[np*2][0] = t4[0]; bH[np*2][1] = t4[1];
                bH[np*2+1][0] = t4[2]; bH[np*2+1][1] = t4[3];
                LDSM4(t4, bd + 10240);
                bL[np*2][0] = t4[0]; bL[np*2][1] = t4[1];
                bL[np*2+1][0] = t4[2]; bL[np*2+1][1] = t4[3];
            }
            #pragma unroll
            for (int mt = 0; mt < 4; mt++)
                #pragma unroll
                for (int nt = 0; nt < 4; nt++)
                    MMA16816(acc[mt][nt], aH[mt], bH[nt]);
            #pragma unroll
            for (int mt = 0; mt < 4; mt++)
                #pragma unroll
                for (int nt = 0; nt < 4; nt++)
                    MMA16816(acc[mt][nt], aH[mt], bL[nt]);
        }
        __syncthreads();
    }

    // ---------------- epilogue ----------------
    int qr = lane >> 2, qc = (lane & 3) * 2;
    #pragma unroll
    for (int mt = 0; mt < 4; mt++) {
        #pragma unroll
        for (int half_ = 0; half_ < 2; half_++) {
            int m = m0 + wm + mt*16 + half_*8 + qr;
            if (m >= M) continue;
            #pragma unroll
            for (int nt = 0; nt < 4; nt++) {
                int cl = wn + nt*8 + qc;
                int n = n0 + cl;
                if (n >= N) continue;
                float v0 = acc[mt][nt][half_*2 + 0] + biass[cl];
                float v1 = acc[mt][nt][half_*2 + 1] + biass[cl + 1];
                if (MODE == 0) {
                    *(float2*)(C + (size_t)m * N + n) = make_float2(v0, v1);
                } else if (MODE == 1) {
                    __half2 p = __floats2half2_rn(fmaxf(v0, 0.f), fmaxf(v1, 0.f));
                    *(__half2*)(Ch + (size_t)m * N + n) = p;
                } else if (MODE == 2) {
                    int lq = m >> 3, b = m & 7;
                    int part = n >> 8, h = (n >> 5) & 7, d = n & 31;
                    size_t o = ((((size_t)lq * NH_ + h) * 8) + b) * HD_ + d;
                    __half* dstb = (part == 0) ? g_Q : (part == 1) ? g_K : g_Vv;
                    *(__half2*)(dstb + o) = __floats2half2_rn(v0, v1);
                } else if (MODE == 3) {
                    int b = m / LIN_, lin = m - b * LIN_;
                    int h = n >> 5, d = n & 31;
                    size_t o = (((size_t)(b*NH_ + h)) * LIN_ + lin) * HD_ + d;
                    *(__half2*)(g_val + o) = __floats2half2_rn(v0, v1);
                } else { // MODE 4
                    if (n < 192)
                        *(float2*)(g_off + (size_t)m * 192 + n) = make_float2(v0, v1);
                    else
                        *(float2*)(g_aw + (size_t)m * 96 + (n - 192)) = make_float2(v0, v1);
                }
            }
        }
    }
}

// ---------------- self-attention over the 8-token axis ----------------
#define ALQ 2
__global__ void __launch_bounds__(128)
attn_kernel()
{
    __shared__ float Ks[ALQ * NH_ * 8 * HD_];
    __shared__ float Vs[ALQ * NH_ * 8 * HD_];

    int lq0 = blockIdx.x * ALQ;
    int t = threadIdx.x;

    const uint4* kg = (const uint4*)(g_K  + (size_t)lq0 * NH_ * 8 * HD_);
    const uint4* vg = (const uint4*)(g_Vv + (size_t)lq0 * NH_ * 8 * HD_);
    #pragma unroll
    for (int f = 0; f < (ALQ * NH_ * 8 * HD_ / 8) / 128; f++) {
        int idx = f * 128 + t;
        uint4 kv = kg[idx], vv = vg[idx];
        const __half2* kh = (const __half2*)&kv;
        const __half2* vh = (const __half2*)&vv;
        float* kd = Ks + idx * 8;
        float* vd = Vs + idx * 8;
        #pragma unroll
        for (int j = 0; j < 4; j++) {
            float2 a = __half22float2(kh[j]); kd[2*j] = a.x; kd[2*j+1] = a.y;
            float2 b = __half22float2(vh[j]); vd[2*j] = b.x; vd[2*j+1] = b.y;
        }
    }
    __syncthreads();

    int lql = t >> 6;
    int r   = t & 63;
    int h   = r >> 3;
    int s   = r & 7;
    int lq  = lq0 + lql;

    const float scale = 0.17677669529663687f;
    float qr[HD_];
    {
        const uint4* Qp = (const uint4*)(g_Q + ((((size_t)lq * NH_ + h) * 8) + s) * HD_);
        #pragma unroll
        for (int i = 0; i < 4; i++) {
            uint4 q4 = Qp[i];
            const __half2* qh = (const __half2*)&q4;
            #pragma unroll
            for (int j = 0; j < 4; j++) {
                float2 a = __half22float2(qh[j]);
                qr[i*8 + 2*j] = a.x; qr[i*8 + 2*j + 1] = a.y;
            }
        }
    }

    const float* Kt = Ks + (lql * NH_ + h) * 8 * HD_;
    const float* Vt = Vs + (lql * NH_ + h) * 8 * HD_;

    float logit[8];
    float mx = -1e30f;
    #pragma unroll
    for (int j = 0; j < 8; j++) {
        float acc = 0.f;
        const float* kp = Kt + j * HD_;
        #pragma unroll
        for (int d = 0; d < HD_; d++) acc = fmaf(qr[d], kp[d], acc);
        logit[j] = acc * scale;
        mx = fmaxf(mx, logit[j]);
    }
    float sum = 0.f;
    #pragma unroll
    for (int j = 0; j < 8; j++) { logit[j] = __expf(logit[j] - mx); sum += logit[j]; }
    float inv = 1.f / sum;

    float accv[HD_];
    #pragma unroll
    for (int d = 0; d < HD_; d++) accv[d] = 0.f;
    #pragma unroll
    for (int j = 0; j < 8; j++) {
        float p = logit[j] * inv;
        const float* vp = Vt + j * HD_;
        #pragma unroll
        for (int d = 0; d < HD_; d++) accv[d] = fmaf(p, vp[d], accv[d]);
    }

    __half* oh = g_act + OFF_CTX + ((size_t)(lq * B_ + s)) * D_ + h * HD_;
    #pragma unroll
    for (int d = 0; d < HD_; d += 2)
        *(__half2*)(oh + d) = __floats2half2_rn(accv[d], accv[d+1]);
}

// ---------------- LayerNorm(x1 + x2), optional fp16 side-output ----------------
__global__ void __launch_bounds__(256)
ln_kernel(const float* __restrict__ x1, const float* __restrict__ x2,
          const float* __restrict__ gam, const float* __restrict__ bet,
          float* __restrict__ out, __half* __restrict__ oh)
{
    int gwarp = (blockIdx.x * blockDim.x + threadIdx.x) >> 5;
    int lane  = threadIdx.x & 31;
    if (gwarp >= ROWS_) return;
    size_t base = (size_t)gwarp * D_ + lane * 8;

    float v[8];
    {
        float4 a0 = *(const float4*)(x1 + base);
        float4 a1 = *(const float4*)(x1 + base + 4);
        float4 b0 = *(const float4*)(x2 + base);
        float4 b1 = *(const float4*)(x2 + base + 4);
        v[0]=a0.x+b0.x; v[1]=a0.y+b0.y; v[2]=a0.z+b0.z; v[3]=a0.w+b0.w;
        v[4]=a1.x+b1.x; v[5]=a1.y+b1.y; v[6]=a1.z+b1.z; v[7]=a1.w+b1.w;
    }
    float s = 0.f, ss = 0.f;
    #pragma unroll
    for (int j = 0; j < 8; j++) { s += v[j]; ss += v[j]*v[j]; }
    #pragma unroll
    for (int o = 16; o > 0; o >>= 1) {
        s  += __shfl_xor_sync(0xffffffffu, s,  o);
        ss += __shfl_xor_sync(0xffffffffu, ss, o);
    }
    float mean = s * (1.f/256.f);
    float var  = ss * (1.f/256.f) - mean*mean;
    float rstd = rsqrtf(var + 1e-5f);

    int c = lane * 8;
    float4 g0 = *(const float4*)(gam + c);
    float4 g1 = *(const float4*)(gam + c + 4);
    float4 e0 = *(const float4*)(bet + c);
    float4 e1 = *(const float4*)(bet + c + 4);
    float ov[8];
    ov[0] = (v[0]-mean)*rstd*g0.x + e0.x;
    ov[1] = (v[1]-mean)*rstd*g0.y + e0.y;
    ov[2] = (v[2]-mean)*rstd*g0.z + e0.z;
    ov[3] = (v[3]-mean)*rstd*g0.w + e0.w;
    ov[4] = (v[4]-mean)*rstd*g1.x + e1.x;
    ov[5] = (v[5]-mean)*rstd*g1.y + e1.y;
    ov[6] = (v[6]-mean)*rstd*g1.z + e1.z;
    ov[7] = (v[7]-mean)*rstd*g1.w + e1.w;
    *(float4*)(out + base)     = make_float4(ov[0], ov[1], ov[2], ov[3]);
    *(float4*)(out + base + 4) = make_float4(ov[4], ov[5], ov[6], ov[7]);

    if (oh) {
        __half2 p0 = __floats2half2_rn(ov[0], ov[1]);
        __half2 p1 = __floats2half2_rn(ov[2], ov[3]);
        __half2 p2 = __floats2half2_rn(ov[4], ov[5]);
        __half2 p3 = __floats2half2_rn(ov[6], ov[7]);
        uint4 pk = make_uint4(*(uint32_t*)&p0, *(uint32_t*)&p1, *(uint32_t*)&p2, *(uint32_t*)&p3);
        *(uint4*)(oh + base) = pk;
    }
}

// ---------------- MS-deformable sampling (fp16 value, fp16 ms output) ----------------
__device__ __forceinline__ float ms_sample(const __half* __restrict__ vb,
                                           int y, int x, int H, int W, int lane)
{
    if (x < 0 || x >= W || y < 0 || y >= H) return 0.f;
    return __half2float(vb[((size_t)(y * W + x)) * HD_ + lane]);
}

__global__ void __launch_bounds__(256)
msdeform_kernel()
{
    int gw = (blockIdx.x * blockDim.x + threadIdx.x) >> 5;
    int lane = threadIdx.x & 31;
    if (gw >= ROWS_ * NH_) return;
    int i = gw >> 3, h = gw & 7;
    int s = i >> 3, b = i & 7;

    float rx = ((s % 60) + 0.5f) * (1.f/60.f);
    float ry = ((s / 60) + 0.5f) * (1.f/60.f);

    const float* awp = g_aw + (size_t)i * 96 + h * 12;
    float wgt[12]; float mx = -1e30f;
    #pragma unroll
    for (int t = 0; t < 12; t++) { wgt[t] = awp[t]; mx = fmaxf(mx, wgt[t]); }
    float sm = 0.f;
    #pragma unroll
    for (int t = 0; t < 12; t++) { wgt[t] = __expf(wgt[t] - mx); sm += wgt[t]; }
    float inv = 1.f / sm;

    const float* offp = g_off + (size_t)i * 192 + h * 24;
    const int Hs[3] = {60, 30, 15};
    const int St[3] = {0, 3600, 4500};

    float acc = 0.f;
    #pragma unroll
    for (int l = 0; l < 3; l++) {
        int Hl = Hs[l], Wl = Hs[l];
        const __half* vb = g_val + (((size_t)(b*NH_ + h)) * LIN_ + St[l]) * HD_;
        #pragma unroll
        for (int p = 0; p < 4; p++) {
            float ox = offp[l*8 + p*2 + 0];
            float oy = offp[l*8 + p*2 + 1];
            float x = (rx + ox / (float)Wl) * (float)Wl - 0.5f;
            float y = (ry + oy / (float)Hl) * (float)Hl - 0.5f;
            float fx0 = floorf(x), fy0 = floorf(y);
            float fx = x - fx0, fy = y - fy0;
            int x0 = (int)fx0, y0 = (int)fy0;
            float a = wgt[l*4 + p] * inv;
            float s00 = ms_sample(vb, y0,   x0,   Hl, Wl, lane);
            float s01 = ms_sample(vb, y0,   x0+1, Hl, Wl, lane);
            float s10 = ms_sample(vb, y0+1, x0,   Hl, Wl, lane);
            float s11 = ms_sample(vb, y0+1, x0+1, Hl, Wl, lane);
            float bil = s00*(1.f-fx)*(1.f-fy) + s01*fx*(1.f-fy)
                      + s10*(1.f-fx)*fy       + s11*fx*fy;
            acc = fmaf(a, bil, acc);
        }
    }
    g_act[OFF_MS + (size_t)i * D_ + h * HD_ + lane] = __float2half_rn(acc);
}

// ---------------- host orchestration ----------------
extern "C" void kernel_launch(void* const* d_in, const int* in_sizes, int n_in,
                              void* d_out, int out_size)
{
    (void)in_sizes; (void)n_in; (void)out_size;
    const float* tgt  = (const float*)d_in[0];
    const float* qp   = (const float*)d_in[1];
    const float* src  = (const float*)d_in[2];
    const float* in_w = (const float*)d_in[5];
    const float* in_b = (const float*)d_in[6];
    const float* ow   = (const float*)d_in[7];
    const float* ob   = (const float*)d_in[8];
    const float* sow  = (const float*)d_in[9];
    const float* sob  = (const float*)d_in[10];
    const float* aww  = (const float*)d_in[11];
    const float* awb  = (const float*)d_in[12];
    const float* vw   = (const float*)d_in[13];
    const float* vb   = (const float*)d_in[14];
    const float* cow  = (const float*)d_in[15];
    const float* cob  = (const float*)d_in[16];
    const float* ln1g = (const float*)d_in[17];
    const float* ln1b = (const float*)d_in[18];
    const float* ln2g = (const float*)d_in[19];
    const float* ln2b = (const float*)d_in[20];
    const float* ln3g = (const float*)d_in[21];
    const float* ln3b = (const float*)d_in[22];
    const float* f1w  = (const float*)d_in[23];
    const float* f1b  = (const float*)d_in[24];
    const float* f2w  = (const float*)d_in[25];
    const float* f2b  = (const float*)d_in[26];
    float* out = (float*)d_out;

    __half *act, *whi, *wlo;
    float *tp, *tmpp, *tqp, *cbp;
    cudaGetSymbolAddress((void**)&act, g_act);
    cudaGetSymbolAddress((void**)&whi, g_whi);
    cudaGetSymbolAddress((void**)&wlo, g_wlo);
    cudaGetSymbolAddress((void**)&tp,   g_t);
    cudaGetSymbolAddress((void**)&tmpp, g_tmp);
    cudaGetSymbolAddress((void**)&tqp,  g_tq);
    cudaGetSymbolAddress((void**)&cbp,  g_cball);

    cudaFuncSetAttribute(gemm_mma<0>, cudaFuncAttributeMaxDynamicSharedMemorySize, GSMEM);
    cudaFuncSetAttribute(gemm_mma<1>, cudaFuncAttributeMaxDynamicSharedMemorySize, GSMEM);
    cudaFuncSetAttribute(gemm_mma<2>, cudaFuncAttributeMaxDynamicSharedMemorySize, GSMEM);
    cudaFuncSetAttribute(gemm_mma<3>, cudaFuncAttributeMaxDynamicSharedMemorySize, GSMEM);
    cudaFuncSetAttribute(gemm_mma<4>, cudaFuncAttributeMaxDynamicSharedMemorySize, GSMEM);

    // ---- setup ----
    CbArgs ca;
    ca.W[0]=in_w; ca.Bv[0]=in_b; ca.N[0]=768;  ca.K[0]=256;  ca.lim[0]=512;
    ca.W[1]=ow;   ca.Bv[1]=ob;   ca.N[1]=256;  ca.K[1]=256;  ca.lim[1]=0;
    ca.W[2]=vw;   ca.Bv[2]=vb;   ca.N[2]=256;  ca.K[2]=256;  ca.lim[2]=0;
    ca.W[3]=sow;  ca.Bv[3]=sob;  ca.N[3]=192;  ca.K[3]=256;  ca.lim[3]=192;
    ca.W[4]=aww;  ca.Bv[4]=awb;  ca.N[4]=96;   ca.K[4]=256;  ca.lim[4]=96;
    ca.W[5]=cow;  ca.Bv[5]=cob;  ca.N[5]=256;  ca.K[5]=256;  ca.lim[5]=0;
    ca.W[6]=f1w;  ca.Bv[6]=f1b;  ca.N[6]=1024; ca.K[6]=256;  ca.lim[6]=0;
    ca.W[7]=f2w;  ca.Bv[7]=f2b;  ca.N[7]=256;  ca.K[7]=1024; ca.lim[7]=0;
    cb_kernel<<<64, 128>>>(ca, qp);

    WArgs wa;
    wa.p[0]=in_w; wa.p[1]=ow; wa.p[2]=vw; wa.p[3]=sow;
    wa.p[4]=aww;  wa.p[5]=cow; wa.p[6]=f1w; wa.p[7]=f2w;
    cvtw_kernel<<<(WARENA/4 + 255)/256, 256>>>(wa);
    cvta_kernel<<<((SZ_TGT+SZ_SRC)/4 + 255)/256, 256>>>(tgt, src);

    const int MT  = 225;   // 28800/128
    const int VMT = 296;   // ceil(37800/128)

    // 1) QKV projection (qp folded into Q/K bias), fp16 scatter
    gemm_mma<2><<<dim3(MT, 6), 256, GSMEM>>>(act+OFF_TGT, whi+WOFF_IN, wlo+WOFF_IN,
                                             nullptr, nullptr, cbp+0*1024, ROWS_, 768, 256);
    // 2) tiny self-attention
    attn_kernel<<<LQ_/ALQ, 128>>>();
    // 3) out projection + ln2
    gemm_mma<0><<<dim3(MT, 2), 256, GSMEM>>>(act+OFF_CTX, whi+WOFF_OW, wlo+WOFF_OW,
                                             tmpp, nullptr, cbp+1*1024, ROWS_, 256, 256);
    ln_kernel<<<ROWS_/8, 256>>>(tgt, tmpp, ln2g, ln2b, tp, act+OFF_T);
    // 4) value projection (fp16 scatter) + merged off/aw GEMM (N=288)
    gemm_mma<3><<<dim3(VMT, 2), 256, GSMEM>>>(act+OFF_SRC, whi+WOFF_VW, wlo+WOFF_VW,
                                              nullptr, nullptr, cbp+2*1024, VROWS_, 256, 256);
    gemm_mma<4><<<dim3(MT, 3), 256, GSMEM>>>(act+OFF_T, whi+WOFF_SOW, wlo+WOFF_SOW,
                                             nullptr, nullptr, cbp+3*1024, ROWS_, 288, 256);
    // 5) sampling + cross projection + ln1
    msdeform_kernel<<<ROWS_, 256>>>();
    gemm_mma<0><<<dim3(MT, 2), 256, GSMEM>>>(act+OFF_MS, whi+WOFF_COW, wlo+WOFF_COW,
                                             tmpp, nullptr, cbp+5*1024, ROWS_, 256, 256);
    ln_kernel<<<ROWS_/8, 256>>>(tp, tmpp, ln1g, ln1b, tqp, act+OFF_TQ);
    // 6) FFN + ln3
    gemm_mma<1><<<dim3(MT, 8), 256, GSMEM>>>(act+OFF_TQ, whi+WOFF_F1, wlo+WOFF_F1,
                                             nullptr, act+OFF_FFN, cbp+6*1024, ROWS_, 1024, 256);
    gemm_mma<0><<<dim3(MT, 2), 256, GSMEM>>>(act+OFF_FFN, whi+WOFF_F2, wlo+WOFF_F2,
                                             tmpp, nullptr, cbp+7*1024, ROWS_, 256, 1024);
    ln_kernel<<<ROWS_/8, 256>>>(tqp, tmpp, ln3g, ln3b, out, nullptr);
}

// round 13
// speedup vs baseline: 3.1347x; 1.1803x over previous
#include <cuda_runtime.h>
#include <cuda_fp16.h>
#include <stdint.h>
#include <math.h>

// ---------------- problem constants ----------------
#define D_    256
#define NH_   8
#define HD_   32
#define B_    8
#define LQ_   3600
#define LIN_  4725
#define ROWS_ (LQ_*B_)       // 28800
#define VROWS_ (B_*LIN_)     // 37800
#define DFF_  1024

// ---------------- fp16 activation arena ----------------
#define SZ_TGT (ROWS_*D_)
#define SZ_SRC (VROWS_*D_)
#define SZ_RC  (ROWS_*D_)
#define SZ_FFN (ROWS_*DFF_)
#define OFF_TGT 0
#define OFF_SRC (OFF_TGT+SZ_TGT)
#define OFF_CTX (OFF_SRC+SZ_SRC)
#define OFF_T   (OFF_CTX+SZ_RC)
#define OFF_MS  (OFF_T+SZ_RC)
#define OFF_TQ  (OFF_MS+SZ_RC)
#define OFF_FFN (OFF_TQ+SZ_RC)
#define ARENA_SZ (OFF_FFN+SZ_FFN)

__device__ __align__(256) __half g_act[ARENA_SZ];

// weight arena (single fp16; sow and aww adjacent -> merged N=288 GEMM)
#define WOFF_IN  0
#define WOFF_OW  (WOFF_IN+768*256)
#define WOFF_VW  (WOFF_OW+256*256)
#define WOFF_SOW (WOFF_VW+256*256)
#define WOFF_AWW (WOFF_SOW+192*256)
#define WOFF_COW (WOFF_AWW+96*256)
#define WOFF_F1  (WOFF_COW+256*256)
#define WOFF_F2  (WOFF_F1+1024*256)
#define WARENA   (WOFF_F2+256*1024)
__device__ __align__(256) __half g_whi[WARENA];

// scratch
__device__ __align__(256) __half g_Q  [(size_t)LQ_*NH_*8*HD_];
__device__ __align__(256) __half g_K  [(size_t)LQ_*NH_*8*HD_];
__device__ __align__(256) __half g_Vv [(size_t)LQ_*NH_*8*HD_];
__device__ __align__(256) __half g_val[(size_t)B_*NH_*LIN_*HD_];
__device__ __align__(256) float g_t  [(size_t)ROWS_*D_];
__device__ __align__(256) float g_tmp[(size_t)ROWS_*D_];
__device__ __align__(256) float g_tq [(size_t)ROWS_*D_];
__device__ __align__(256) float g_off[(size_t)ROWS_*192];
__device__ __align__(256) float g_aw [(size_t)ROWS_*96];
__device__ __align__(256) float g_cball[8*1024];

// ---------------- helpers ----------------
__device__ __forceinline__ uint32_t smem_u32(const void* p){
    uint32_t a;
    asm("{ .reg .u64 t; cvta.to.shared.u64 t, %1; cvt.u32.u64 %0, t; }" : "=r"(a) : "l"(p));
    return a;
}

#define LDSM4(r, addr) \
    asm volatile("ldmatrix.sync.aligned.m8n8.x4.shared.b16 {%0,%1,%2,%3}, [%4];" \
        : "=r"((r)[0]), "=r"((r)[1]), "=r"((r)[2]), "=r"((r)[3]) : "r"(addr))

#define MMA16816(d, a, b) \
    asm volatile("mma.sync.aligned.m16n8k16.row.col.f32.f16.f16.f32 " \
        "{%0,%1,%2,%3}, {%4,%5,%6,%7}, {%8,%9}, {%0,%1,%2,%3};" \
        : "+f"((d)[0]), "+f"((d)[1]), "+f"((d)[2]), "+f"((d)[3]) \
        : "r"((a)[0]), "r"((a)[1]), "r"((a)[2]), "r"((a)[3]), "r"((b)[0]), "r"((b)[1]))

#define CPA16(sa, ga) asm volatile("cp.async.cg.shared.global [%0], [%1], 16;" :: "r"(sa), "l"(ga))
#define CPA_COMMIT()  asm volatile("cp.async.commit_group;")

// ---------------- setup: all 8 column-bias vectors ----------------
struct CbArgs { const float* W[8]; const float* Bv[8]; int N[8]; int K[8]; int lim[8]; };
__global__ void cb_kernel(CbArgs a, const float* __restrict__ qp)
{
    int g = blockIdx.x * 128 + threadIdx.x;
    int seg = g >> 10, n = g & 1023;
    if (n >= a.N[seg]) return;
    float v = a.Bv[seg][n];
    if (n < a.lim[seg]) {
        const float* w = a.W[seg] + (size_t)n * a.K[seg];
        float acc = 0.f;
        for (int k = 0; k < a.K[seg]; k += 4) {
            float4 wv = *(const float4*)(w + k);
            float4 qv = *(const float4*)(qp + k);
            acc += wv.x*qv.x + wv.y*qv.y + wv.z*qv.z + wv.w*qv.w;
        }
        v += acc;
    }
    int dst = (seg == 4) ? (3*1024 + 192 + n) : (seg*1024 + n);
    g_cball[dst] = v;
}

// ---------------- weight fp32 -> fp16 ----------------
struct WArgs { const float* p[8]; };
__global__ void cvtw_kernel(WArgs a)
{
    int e = (blockIdx.x * 256 + threadIdx.x) * 4;
    if (e >= WARENA) return;
    const int offs[9] = {0,196608,262144,327680,376832,401408,466944,729088,991232};
    int seg = 0;
    #pragma unroll
    for (int s = 1; s < 8; s++) if (e >= offs[s]) seg = s;
    float4 v = *(const float4*)(a.p[seg] + (e - offs[seg]));
    __half2 p0 = __floats2half2_rn(v.x, v.y);
    __half2 p1 = __floats2half2_rn(v.z, v.w);
    *(uint2*)(g_whi+e) = make_uint2(*(uint32_t*)&p0, *(uint32_t*)&p1);
}

// ---------------- activation inputs (tgt, src) -> fp16 ----------------
__global__ void cvta_kernel(const float* __restrict__ tgt, const float* __restrict__ src)
{
    int e = (blockIdx.x * 256 + threadIdx.x) * 4;
    if (e >= SZ_TGT + SZ_SRC) return;
    const float* sp; int dst;
    if (e < SZ_TGT) { sp = tgt + e; dst = OFF_TGT + e; }
    else            { sp = src + (e - SZ_TGT); dst = OFF_SRC + (e - SZ_TGT); }
    float4 v = *(const float4*)sp;
    __half2 p0 = __floats2half2_rn(v.x, v.y);
    __half2 p1 = __floats2half2_rn(v.z, v.w);
    *(uint2*)(g_act+dst) = make_uint2(*(uint32_t*)&p0, *(uint32_t*)&p1);
}

// ---------------- mma.sync GEMM: C[m,n] = A[m,:]·W[n,:] + cb[n] ----------------
// single fp16 term, 128x128 tile, 8 warps (2M x 4N), BK=32, 3-stage cp.async.
// Stage (80B rows): A@0 W@10240, stage stride 20480, 3 stages.
// MODE 0: fp32   MODE 1: relu->fp16   MODE 2: QKV scatter (fp16)
// MODE 3: value scatter (fp16)   MODE 4: off/aw split scatter (fp32)
#define GSMEM (3*20480 + 512)

template<int MODE>
__global__ void __launch_bounds__(256)
gemm_mma(const __half* __restrict__ A, const __half* __restrict__ W,
         float* __restrict__ C, __half* __restrict__ Ch,
         const float* __restrict__ cb, int M, int N, int K)
{
    extern __shared__ __align__(16) char smc[];
    uint32_t sb = smem_u32(smc);
    float* biass = (float*)(smc + 61440);
    int tid = threadIdx.x, wid = tid >> 5, lane = tid & 31;
    int m0 = blockIdx.x * 128, n0 = blockIdx.y * 128;

    if (tid < 128) biass[tid] = cb[n0 + tid];

    float acc[4][4][4];
    #pragma unroll
    for (int i = 0; i < 4; i++)
        #pragma unroll
        for (int j = 0; j < 4; j++)
            #pragma unroll
            for (int e = 0; e < 4; e++) acc[i][j][e] = 0.f;

    const int NC = K >> 5;
    const int wm = (wid & 1) * 64, wn = (wid >> 1) * 32;

    auto stage_load = [&](int c, int st) {
        size_t kb = (size_t)c * 32;
        uint32_t base = sb + st * 20480;
        #pragma unroll
        for (int i = 0; i < 4; i++) {
            int chunk = tid + i * 256;            // 0..1023
            int mat = chunk >> 9;                 // 0=A 1=W
            int idx = chunk & 511;
            int row = idx >> 2, cc = idx & 3;
            uint32_t sa = base + mat*10240 + row*80 + cc*16;
            const __half* gp;
            bool valid;
            if (mat == 0) {
                int gm = m0 + row; valid = gm < M;
                gp = A + ((size_t)(valid ? gm : 0) * K + kb + cc*8);
            } else {
                int gn = n0 + row; valid = gn < N;
                gp = W + ((size_t)(valid ? gn : 0) * K + kb + cc*8);
            }
            if (valid) CPA16(sa, gp);
            else       asm volatile("st.shared.v4.b32 [%0], {%1,%1,%1,%1};" :: "r"(sa), "r"(0u));
        }
        CPA_COMMIT();
    };

    stage_load(0, 0);
    if (NC > 1) stage_load(1, 1);

    for (int c = 0; c < NC; c++) {
        if (c + 2 < NC) {
            stage_load(c + 2, (c + 2) % 3);
            asm volatile("cp.async.wait_group 2;");
        } else if (c + 1 < NC) {
            asm volatile("cp.async.wait_group 1;");
        } else {
            asm volatile("cp.async.wait_group 0;");
        }
        __syncthreads();

        uint32_t ab = sb + (c % 3) * 20480;
        int g = lane >> 3, li = lane & 7;
        #pragma unroll
        for (int k16 = 0; k16 < 2; k16++) {
            uint32_t aH[4][4], bH[4][2];
            #pragma unroll
            for (int mt = 0; mt < 4; mt++) {
                int row = wm + mt*16 + (g & 1)*8 + li;
                uint32_t ad = ab + row*80 + k16*32 + (g >> 1)*16;
                LDSM4(aH[mt], ad);
            }
            #pragma unroll
            for (int np = 0; np < 2; np++) {
                int row = wn + np*16 + ((lane >= 16) ? 8 : 0) + li;
                uint32_t bd = ab + 10240 + row*80 + k16*32 + ((lane >> 3) & 1)*16;
                uint32_t t4[4];
                LDSM4(t4, bd);
                bH[np*2][0] = t4[0]; bH[np*2][1] = t4[1];
                bH[np*2+1][0] = t4[2]; bH[np*2+1][1] = t4[3];
            }
            #pragma unroll
            for (int mt = 0; mt < 4; mt++)
                #pragma unroll
                for (int nt = 0; nt < 4; nt++)
                    MMA16816(acc[mt][nt], aH[mt], bH[nt]);
        }
        __syncthreads();
    }

    // ---------------- epilogue ----------------
    int qr = lane >> 2, qc = (lane & 3) * 2;
    #pragma unroll
    for (int mt = 0; mt < 4; mt++) {
        #pragma unroll
        for (int half_ = 0; half_ < 2; half_++) {
            int m = m0 + wm + mt*16 + half_*8 + qr;
            if (m >= M) continue;
            #pragma unroll
            for (int nt = 0; nt < 4; nt++) {
                int cl = wn + nt*8 + qc;
                int n = n0 + cl;
                if (n >= N) continue;
                float v0 = acc[mt][nt][half_*2 + 0] + biass[cl];
                float v1 = acc[mt][nt][half_*2 + 1] + biass[cl + 1];
                if (MODE == 0) {
                    *(float2*)(C + (size_t)m * N + n) = make_float2(v0, v1);
                } else if (MODE == 1) {
                    __half2 p = __floats2half2_rn(fmaxf(v0, 0.f), fmaxf(v1, 0.f));
                    *(__half2*)(Ch + (size_t)m * N + n) = p;
                } else if (MODE == 2) {
                    int lq = m >> 3, b = m & 7;
                    int part = n >> 8, h = (n >> 5) & 7, d = n & 31;
                    size_t o = ((((size_t)lq * NH_ + h) * 8) + b) * HD_ + d;
                    __half* dstb = (part == 0) ? g_Q : (part == 1) ? g_K : g_Vv;
                    *(__half2*)(dstb + o) = __floats2half2_rn(v0, v1);
                } else if (MODE == 3) {
                    int b = m / LIN_, lin = m - b * LIN_;
                    int h = n >> 5, d = n & 31;
                    size_t o = (((size_t)(b*NH_ + h)) * LIN_ + lin) * HD_ + d;
                    *(__half2*)(g_val + o) = __floats2half2_rn(v0, v1);
                } else { // MODE 4
                    if (n < 192)
                        *(float2*)(g_off + (size_t)m * 192 + n) = make_float2(v0, v1);
                    else
                        *(float2*)(g_aw + (size_t)m * 96 + (n - 192)) = make_float2(v0, v1);
                }
            }
        }
    }
}

// ---------------- self-attention over the 8-token axis ----------------
#define ALQ 2
__global__ void __launch_bounds__(128)
attn_kernel()
{
    __shared__ float Ks[ALQ * NH_ * 8 * HD_];
    __shared__ float Vs[ALQ * NH_ * 8 * HD_];

    int lq0 = blockIdx.x * ALQ;
    int t = threadIdx.x;

    const uint4* kg = (const uint4*)(g_K  + (size_t)lq0 * NH_ * 8 * HD_);
    const uint4* vg = (const uint4*)(g_Vv + (size_t)lq0 * NH_ * 8 * HD_);
    #pragma unroll
    for (int f = 0; f < (ALQ * NH_ * 8 * HD_ / 8) / 128; f++) {
        int idx = f * 128 + t;
        uint4 kv = kg[idx], vv = vg[idx];
        const __half2* kh = (const __half2*)&kv;
        const __half2* vh = (const __half2*)&vv;
        float* kd = Ks + idx * 8;
        float* vd = Vs + idx * 8;
        #pragma unroll
        for (int j = 0; j < 4; j++) {
            float2 a = __half22float2(kh[j]); kd[2*j] = a.x; kd[2*j+1] = a.y;
            float2 b = __half22float2(vh[j]); vd[2*j] = b.x; vd[2*j+1] = b.y;
        }
    }
    __syncthreads();

    int lql = t >> 6;
    int r   = t & 63;
    int h   = r >> 3;
    int s   = r & 7;
    int lq  = lq0 + lql;

    const float scale = 0.17677669529663687f;
    float qr[HD_];
    {
        const uint4* Qp = (const uint4*)(g_Q + ((((size_t)lq * NH_ + h) * 8) + s) * HD_);
        #pragma unroll
        for (int i = 0; i < 4; i++) {
            uint4 q4 = Qp[i];
            const __half2* qh = (const __half2*)&q4;
            #pragma unroll
            for (int j = 0; j < 4; j++) {
                float2 a = __half22float2(qh[j]);
                qr[i*8 + 2*j] = a.x; qr[i*8 + 2*j + 1] = a.y;
            }
        }
    }

    const float* Kt = Ks + (lql * NH_ + h) * 8 * HD_;
    const float* Vt = Vs + (lql * NH_ + h) * 8 * HD_;

    float logit[8];
    float mx = -1e30f;
    #pragma unroll
    for (int j = 0; j < 8; j++) {
        float acc = 0.f;
        const float* kp = Kt + j * HD_;
        #pragma unroll
        for (int d = 0; d < HD_; d++) acc = fmaf(qr[d], kp[d], acc);
        logit[j] = acc * scale;
        mx = fmaxf(mx, logit[j]);
    }
    float sum = 0.f;
    #pragma unroll
    for (int j = 0; j < 8; j++) { logit[j] = __expf(logit[j] - mx); sum += logit[j]; }
    float inv = 1.f / sum;

    float accv[HD_];
    #pragma unroll
    for (int d = 0; d < HD_; d++) accv[d] = 0.f;
    #pragma unroll
    for (int j = 0; j < 8; j++) {
        float p = logit[j] * inv;
        const float* vp = Vt + j * HD_;
        #pragma unroll
        for (int d = 0; d < HD_; d++) accv[d] = fmaf(p, vp[d], accv[d]);
    }

    __half* oh = g_act + OFF_CTX + ((size_t)(lq * B_ + s)) * D_ + h * HD_;
    #pragma unroll
    for (int d = 0; d < HD_; d += 2)
        *(__half2*)(oh + d) = __floats2half2_rn(accv[d], accv[d+1]);
}

// ---------------- LayerNorm(x1 + x2), optional fp16 side-output ----------------
__global__ void __launch_bounds__(256)
ln_kernel(const float* __restrict__ x1, const float* __restrict__ x2,
          const float* __restrict__ gam, const float* __restrict__ bet,
          float* __restrict__ out, __half* __restrict__ oh)
{
    int gwarp = (blockIdx.x * blockDim.x + threadIdx.x) >> 5;
    int lane  = threadIdx.x & 31;
    if (gwarp >= ROWS_) return;
    size_t base = (size_t)gwarp * D_ + lane * 8;

    float v[8];
    {
        float4 a0 = *(const float4*)(x1 + base);
        float4 a1 = *(const float4*)(x1 + base + 4);
        float4 b0 = *(const float4*)(x2 + base);
        float4 b1 = *(const float4*)(x2 + base + 4);
        v[0]=a0.x+b0.x; v[1]=a0.y+b0.y; v[2]=a0.z+b0.z; v[3]=a0.w+b0.w;
        v[4]=a1.x+b1.x; v[5]=a1.y+b1.y; v[6]=a1.z+b1.z; v[7]=a1.w+b1.w;
    }
    float s = 0.f, ss = 0.f;
    #pragma unroll
    for (int j = 0; j < 8; j++) { s += v[j]; ss += v[j]*v[j]; }
    #pragma unroll
    for (int o = 16; o > 0; o >>= 1) {
        s  += __shfl_xor_sync(0xffffffffu, s,  o);
        ss += __shfl_xor_sync(0xffffffffu, ss, o);
    }
    float mean = s * (1.f/256.f);
    float var  = ss * (1.f/256.f) - mean*mean;
    float rstd = rsqrtf(var + 1e-5f);

    int c = lane * 8;
    float4 g0 = *(const float4*)(gam + c);
    float4 g1 = *(const float4*)(gam + c + 4);
    float4 e0 = *(const float4*)(bet + c);
    float4 e1 = *(const float4*)(bet + c + 4);
    float ov[8];
    ov[0] = (v[0]-mean)*rstd*g0.x + e0.x;
    ov[1] = (v[1]-mean)*rstd*g0.y + e0.y;
    ov[2] = (v[2]-mean)*rstd*g0.z + e0.z;
    ov[3] = (v[3]-mean)*rstd*g0.w + e0.w;
    ov[4] = (v[4]-mean)*rstd*g1.x + e1.x;
    ov[5] = (v[5]-mean)*rstd*g1.y + e1.y;
    ov[6] = (v[6]-mean)*rstd*g1.z + e1.z;
    ov[7] = (v[7]-mean)*rstd*g1.w + e1.w;
    *(float4*)(out + base)     = make_float4(ov[0], ov[1], ov[2], ov[3]);
    *(float4*)(out + base + 4) = make_float4(ov[4], ov[5], ov[6], ov[7]);

    if (oh) {
        __half2 p0 = __floats2half2_rn(ov[0], ov[1]);
        __half2 p1 = __floats2half2_rn(ov[2], ov[3]);
        __half2 p2 = __floats2half2_rn(ov[4], ov[5]);
        __half2 p3 = __floats2half2_rn(ov[6], ov[7]);
        uint4 pk = make_uint4(*(uint32_t*)&p0, *(uint32_t*)&p1, *(uint32_t*)&p2, *(uint32_t*)&p3);
        *(uint4*)(oh + base) = pk;
    }
}

// ---------------- MS-deformable sampling (fp16 value, fp16 ms output) ----------------
__device__ __forceinline__ float ms_sample(const __half* __restrict__ vb,
                                           int y, int x, int H, int W, int lane)
{
    if (x < 0 || x >= W || y < 0 || y >= H) return 0.f;
    return __half2float(vb[((size_t)(y * W + x)) * HD_ + lane]);
}

__global__ void __launch_bounds__(256)
msdeform_kernel()
{
    int gw = (blockIdx.x * blockDim.x + threadIdx.x) >> 5;
    int lane = threadIdx.x & 31;
    if (gw >= ROWS_ * NH_) return;
    int i = gw >> 3, h = gw & 7;
    int s = i >> 3, b = i & 7;

    float rx = ((s % 60) + 0.5f) * (1.f/60.f);
    float ry = ((s / 60) + 0.5f) * (1.f/60.f);

    const float* awp = g_aw + (size_t)i * 96 + h * 12;
    float wgt[12]; float mx = -1e30f;
    #pragma unroll
    for (int t = 0; t < 12; t++) { wgt[t] = awp[t]; mx = fmaxf(mx, wgt[t]); }
    float sm = 0.f;
    #pragma unroll
    for (int t = 0; t < 12; t++) { wgt[t] = __expf(wgt[t] - mx); sm += wgt[t]; }
    float inv = 1.f / sm;

    const float* offp = g_off + (size_t)i * 192 + h * 24;
    const int Hs[3] = {60, 30, 15};
    const int St[3] = {0, 3600, 4500};

    float acc = 0.f;
    #pragma unroll
    for (int l = 0; l < 3; l++) {
        int Hl = Hs[l], Wl = Hs[l];
        const __half* vb = g_val + (((size_t)(b*NH_ + h)) * LIN_ + St[l]) * HD_;
        #pragma unroll
        for (int p = 0; p < 4; p++) {
            float ox = offp[l*8 + p*2 + 0];
            float oy = offp[l*8 + p*2 + 1];
            float x = (rx + ox / (float)Wl) * (float)Wl - 0.5f;
            float y = (ry + oy / (float)Hl) * (float)Hl - 0.5f;
            float fx0 = floorf(x), fy0 = floorf(y);
            float fx = x - fx0, fy = y - fy0;
            int x0 = (int)fx0, y0 = (int)fy0;
            float a = wgt[l*4 + p] * inv;
            float s00 = ms_sample(vb, y0,   x0,   Hl, Wl, lane);
            float s01 = ms_sample(vb, y0,   x0+1, Hl, Wl, lane);
            float s10 = ms_sample(vb, y0+1, x0,   Hl, Wl, lane);
            float s11 = ms_sample(vb, y0+1, x0+1, Hl, Wl, lane);
            float bil = s00*(1.f-fx)*(1.f-fy) + s01*fx*(1.f-fy)
                      + s10*(1.f-fx)*fy       + s11*fx*fy;
            acc = fmaf(a, bil, acc);
        }
    }
    g_act[OFF_MS + (size_t)i * D_ + h * HD_ + lane] = __float2half_rn(acc);
}

// ---------------- host orchestration ----------------
extern "C" void kernel_launch(void* const* d_in, const int* in_sizes, int n_in,
                              void* d_out, int out_size)
{
    (void)in_sizes; (void)n_in; (void)out_size;
    const float* tgt  = (const float*)d_in[0];
    const float* qp   = (const float*)d_in[1];
    const float* src  = (const float*)d_in[2];
    const float* in_w = (const float*)d_in[5];
    const float* in_b = (const float*)d_in[6];
    const float* ow   = (const float*)d_in[7];
    const float* ob   = (const float*)d_in[8];
    const float* sow  = (const float*)d_in[9];
    const float* sob  = (const float*)d_in[10];
    const float* aww  = (const float*)d_in[11];
    const float* awb  = (const float*)d_in[12];
    const float* vw   = (const float*)d_in[13];
    const float* vb   = (const float*)d_in[14];
    const float* cow  = (const float*)d_in[15];
    const float* cob  = (const float*)d_in[16];
    const float* ln1g = (const float*)d_in[17];
    const float* ln1b = (const float*)d_in[18];
    const float* ln2g = (const float*)d_in[19];
    const float* ln2b = (const float*)d_in[20];
    const float* ln3g = (const float*)d_in[21];
    const float* ln3b = (const float*)d_in[22];
    const float* f1w  = (const float*)d_in[23];
    const float* f1b  = (const float*)d_in[24];
    const float* f2w  = (const float*)d_in[25];
    const float* f2b  = (const float*)d_in[26];
    float* out = (float*)d_out;

    __half *act, *whi;
    float *tp, *tmpp, *tqp, *cbp;
    cudaGetSymbolAddress((void**)&act, g_act);
    cudaGetSymbolAddress((void**)&whi, g_whi);
    cudaGetSymbolAddress((void**)&tp,   g_t);
    cudaGetSymbolAddress((void**)&tmpp, g_tmp);
    cudaGetSymbolAddress((void**)&tqp,  g_tq);
    cudaGetSymbolAddress((void**)&cbp,  g_cball);

    cudaFuncSetAttribute(gemm_mma<0>, cudaFuncAttributeMaxDynamicSharedMemorySize, GSMEM);
    cudaFuncSetAttribute(gemm_mma<1>, cudaFuncAttributeMaxDynamicSharedMemorySize, GSMEM);
    cudaFuncSetAttribute(gemm_mma<2>, cudaFuncAttributeMaxDynamicSharedMemorySize, GSMEM);
    cudaFuncSetAttribute(gemm_mma<3>, cudaFuncAttributeMaxDynamicSharedMemorySize, GSMEM);
    cudaFuncSetAttribute(gemm_mma<4>, cudaFuncAttributeMaxDynamicSharedMemorySize, GSMEM);

    // ---- setup ----
    CbArgs ca;
    ca.W[0]=in_w; ca.Bv[0]=in_b; ca.N[0]=768;  ca.K[0]=256;  ca.lim[0]=512;
    ca.W[1]=ow;   ca.Bv[1]=ob;   ca.N[1]=256;  ca.K[1]=256;  ca.lim[1]=0;
    ca.W[2]=vw;   ca.Bv[2]=vb;   ca.N[2]=256;  ca.K[2]=256;  ca.lim[2]=0;
    ca.W[3]=sow;  ca.Bv[3]=sob;  ca.N[3]=192;  ca.K[3]=256;  ca.lim[3]=192;
    ca.W[4]=aww;  ca.Bv[4]=awb;  ca.N[4]=96;   ca.K[4]=256;  ca.lim[4]=96;
    ca.W[5]=cow;  ca.Bv[5]=cob;  ca.N[5]=256;  ca.K[5]=256;  ca.lim[5]=0;
    ca.W[6]=f1w;  ca.Bv[6]=f1b;  ca.N[6]=1024; ca.K[6]=256;  ca.lim[6]=0;
    ca.W[7]=f2w;  ca.Bv[7]=f2b;  ca.N[7]=256;  ca.K[7]=1024; ca.lim[7]=0;
    cb_kernel<<<64, 128>>>(ca, qp);

    WArgs wa;
    wa.p[0]=in_w; wa.p[1]=ow; wa.p[2]=vw; wa.p[3]=sow;
    wa.p[4]=aww;  wa.p[5]=cow; wa.p[6]=f1w; wa.p[7]=f2w;
    cvtw_kernel<<<(WARENA/4 + 255)/256, 256>>>(wa);
    cvta_kernel<<<((SZ_TGT+SZ_SRC)/4 + 255)/256, 256>>>(tgt, src);

    const int MT  = 225;   // 28800/128
    const int VMT = 296;   // ceil(37800/128)

    // 1) QKV projection (qp folded into Q/K bias), fp16 scatter
    gemm_mma<2><<<dim3(MT, 6), 256, GSMEM>>>(act+OFF_TGT, whi+WOFF_IN,
                                             nullptr, nullptr, cbp+0*1024, ROWS_, 768, 256);
    // 2) tiny self-attention
    attn_kernel<<<LQ_/ALQ, 128>>>();
    // 3) out projection + ln2
    gemm_mma<0><<<dim3(MT, 2), 256, GSMEM>>>(act+OFF_CTX, whi+WOFF_OW,
                                             tmpp, nullptr, cbp+1*1024, ROWS_, 256, 256);
    ln_kernel<<<ROWS_/8, 256>>>(tgt, tmpp, ln2g, ln2b, tp, act+OFF_T);
    // 4) value projection (fp16 scatter) + merged off/aw GEMM (N=288)
    gemm_mma<3><<<dim3(VMT, 2), 256, GSMEM>>>(act+OFF_SRC, whi+WOFF_VW,
                                              nullptr, nullptr, cbp+2*1024, VROWS_, 256, 256);
    gemm_mma<4><<<dim3(MT, 3), 256, GSMEM>>>(act+OFF_T, whi+WOFF_SOW,
                                             nullptr, nullptr, cbp+3*1024, ROWS_, 288, 256);
    // 5) sampling + cross projection + ln1
    msdeform_kernel<<<ROWS_, 256>>>();
    gemm_mma<0><<<dim3(MT, 2), 256, GSMEM>>>(act+OFF_MS, whi+WOFF_COW,
                                             tmpp, nullptr, cbp+5*1024, ROWS_, 256, 256);
    ln_kernel<<<ROWS_/8, 256>>>(tp, tmpp, ln1g, ln1b, tqp, act+OFF_TQ);
    // 6) FFN + ln3
    gemm_mma<1><<<dim3(MT, 8), 256, GSMEM>>>(act+OFF_TQ, whi+WOFF_F1,
                                             nullptr, act+OFF_FFN, cbp+6*1024, ROWS_, 1024, 256);
    gemm_mma<0><<<dim3(MT, 2), 256, GSMEM>>>(act+OFF_FFN, whi+WOFF_F2,
                                             tmpp, nullptr, cbp+7*1024, ROWS_, 256, 1024);
    ln_kernel<<<ROWS_/8, 256>>>(tqp, tmpp, ln3g, ln3b, out, nullptr);
}

// round 14
// speedup vs baseline: 3.8669x; 1.2336x over previous
#include <cuda_runtime.h>
#include <cuda_fp16.h>
#include <stdint.h>
#include <math.h>

// ---------------- problem constants ----------------
#define D_    256
#define NH_   8
#define HD_   32
#define B_    8
#define LQ_   3600
#define LIN_  4725
#define ROWS_ (LQ_*B_)       // 28800
#define VROWS_ (B_*LIN_)     // 37800
#define DFF_  1024

// ---------------- fp16 activation arena ----------------
#define SZ_TGT (ROWS_*D_)
#define SZ_SRC (VROWS_*D_)
#define SZ_RC  (ROWS_*D_)
#define SZ_FFN (ROWS_*DFF_)
#define OFF_TGT 0
#define OFF_SRC (OFF_TGT+SZ_TGT)
#define OFF_CTX (OFF_SRC+SZ_SRC)
#define OFF_T   (OFF_CTX+SZ_RC)
#define OFF_MS  (OFF_T+SZ_RC)
#define OFF_TQ  (OFF_MS+SZ_RC)
#define OFF_FFN (OFF_TQ+SZ_RC)
#define ARENA_SZ (OFF_FFN+SZ_FFN)

__device__ __align__(256) __half g_act[ARENA_SZ];
__device__ __align__(256) __half g_tmph[(size_t)ROWS_*D_];

// weight arena (single fp16; sow and aww adjacent -> merged N=288 GEMM)
#define WOFF_IN  0
#define WOFF_OW  (WOFF_IN+768*256)
#define WOFF_VW  (WOFF_OW+256*256)
#define WOFF_SOW (WOFF_VW+256*256)
#define WOFF_AWW (WOFF_SOW+192*256)
#define WOFF_COW (WOFF_AWW+96*256)
#define WOFF_F1  (WOFF_COW+256*256)
#define WOFF_F2  (WOFF_F1+1024*256)
#define WARENA   (WOFF_F2+256*1024)
__device__ __align__(256) __half g_whi[WARENA];

// scratch
__device__ __align__(256) __half g_Q  [(size_t)LQ_*NH_*8*HD_];
__device__ __align__(256) __half g_K  [(size_t)LQ_*NH_*8*HD_];
__device__ __align__(256) __half g_Vv [(size_t)LQ_*NH_*8*HD_];
__device__ __align__(256) __half g_val[(size_t)B_*NH_*LIN_*HD_];
__device__ __align__(256) float g_off[(size_t)ROWS_*192];
__device__ __align__(256) float g_aw [(size_t)ROWS_*96];
__device__ __align__(256) float g_cball[8*1024];

// ---------------- helpers ----------------
__device__ __forceinline__ uint32_t smem_u32(const void* p){
    uint32_t a;
    asm("{ .reg .u64 t; cvta.to.shared.u64 t, %1; cvt.u32.u64 %0, t; }" : "=r"(a) : "l"(p));
    return a;
}

#define LDSM4(r, addr) \
    asm volatile("ldmatrix.sync.aligned.m8n8.x4.shared.b16 {%0,%1,%2,%3}, [%4];" \
        : "=r"((r)[0]), "=r"((r)[1]), "=r"((r)[2]), "=r"((r)[3]) : "r"(addr))

#define MMA16816(d, a, b) \
    asm volatile("mma.sync.aligned.m16n8k16.row.col.f32.f16.f16.f32 " \
        "{%0,%1,%2,%3}, {%4,%5,%6,%7}, {%8,%9}, {%0,%1,%2,%3};" \
        : "+f"((d)[0]), "+f"((d)[1]), "+f"((d)[2]), "+f"((d)[3]) \
        : "r"((a)[0]), "r"((a)[1]), "r"((a)[2]), "r"((a)[3]), "r"((b)[0]), "r"((b)[1]))

#define CPA16(sa, ga) asm volatile("cp.async.cg.shared.global [%0], [%1], 16;" :: "r"(sa), "l"(ga))
#define CPA_COMMIT()  asm volatile("cp.async.commit_group;")

// ---------------- merged preprocessing: cvta + cvtw + column biases ----------------
#define NB_CVTA 16650   // (SZ_TGT+SZ_SRC)/4/256
#define NB_CVTW 968     // WARENA/4/256
#define NB_CB   32      // 8192/256
struct PreArgs {
    const float* W[8]; const float* Bv[8];
    int N[8]; int K[8]; int lim[8];
    const float* qp; const float* tgt; const float* src;
};
__global__ void __launch_bounds__(256) pre_kernel(PreArgs a)
{
    int bid = blockIdx.x, tid = threadIdx.x;
    if (bid < NB_CVTA) {
        int e = (bid * 256 + tid) * 4;
        const float* sp; int dst;
        if (e < SZ_TGT) { sp = a.tgt + e; dst = OFF_TGT + e; }
        else            { sp = a.src + (e - SZ_TGT); dst = OFF_SRC + (e - SZ_TGT); }
        float4 v = *(const float4*)sp;
        __half2 p0 = __floats2half2_rn(v.x, v.y);
        __half2 p1 = __floats2half2_rn(v.z, v.w);
        *(uint2*)(g_act+dst) = make_uint2(*(uint32_t*)&p0, *(uint32_t*)&p1);
    } else if (bid < NB_CVTA + NB_CVTW) {
        int e = ((bid - NB_CVTA) * 256 + tid) * 4;
        const int offs[9] = {0,196608,262144,327680,376832,401408,466944,729088,991232};
        int seg = 0;
        #pragma unroll
        for (int s = 1; s < 8; s++) if (e >= offs[s]) seg = s;
        float4 v = *(const float4*)(a.W[seg] + (e - offs[seg]));
        __half2 p0 = __floats2half2_rn(v.x, v.y);
        __half2 p1 = __floats2half2_rn(v.z, v.w);
        *(uint2*)(g_whi+e) = make_uint2(*(uint32_t*)&p0, *(uint32_t*)&p1);
    } else {
        int g = (bid - NB_CVTA - NB_CVTW) * 256 + tid;   // 0..8191
        int seg = g >> 10, n = g & 1023;
        if (n >= a.N[seg]) return;
        float v = a.Bv[seg][n];
        if (n < a.lim[seg]) {
            const float* w = a.W[seg] + (size_t)n * a.K[seg];
            float acc = 0.f;
            for (int k = 0; k < a.K[seg]; k += 4) {
                float4 wv = *(const float4*)(w + k);
                float4 qv = *(const float4*)(a.qp + k);
                acc += wv.x*qv.x + wv.y*qv.y + wv.z*qv.z + wv.w*qv.w;
            }
            v += acc;
        }
        int dst = (seg == 4) ? (3*1024 + 192 + n) : (seg*1024 + n);
        g_cball[dst] = v;
    }
}

// ---------------- mma.sync GEMM: C[m,n] = A[m,:]·W[n,:] + cb[n] ----------------
// single fp16 term, 128x128 tile, 8 warps (2M x 4N), BK=32, 3-stage cp.async.
// MODE 1: relu->fp16   MODE 2: QKV scatter (fp16)   MODE 3: value scatter (fp16)
// MODE 4: off/aw split scatter (fp32)   MODE 5: plain fp16 store
#define GSMEM (3*20480 + 512)

template<int MODE>
__global__ void __launch_bounds__(256)
gemm_mma(const __half* __restrict__ A, const __half* __restrict__ W,
         __half* __restrict__ Ch,
         const float* __restrict__ cb, int M, int N, int K)
{
    extern __shared__ __align__(16) char smc[];
    uint32_t sb = smem_u32(smc);
    float* biass = (float*)(smc + 61440);
    int tid = threadIdx.x, wid = tid >> 5, lane = tid & 31;
    int m0 = blockIdx.x * 128, n0 = blockIdx.y * 128;

    if (tid < 128) biass[tid] = cb[n0 + tid];

    float acc[4][4][4];
    #pragma unroll
    for (int i = 0; i < 4; i++)
        #pragma unroll
        for (int j = 0; j < 4; j++)
            #pragma unroll
            for (int e = 0; e < 4; e++) acc[i][j][e] = 0.f;

    const int NC = K >> 5;
    const int wm = (wid & 1) * 64, wn = (wid >> 1) * 32;

    auto stage_load = [&](int c, int st) {
        size_t kb = (size_t)c * 32;
        uint32_t base = sb + st * 20480;
        #pragma unroll
        for (int i = 0; i < 4; i++) {
            int chunk = tid + i * 256;
            int mat = chunk >> 9;
            int idx = chunk & 511;
            int row = idx >> 2, cc = idx & 3;
            uint32_t sa = base + mat*10240 + row*80 + cc*16;
            const __half* gp;
            bool valid;
            if (mat == 0) {
                int gm = m0 + row; valid = gm < M;
                gp = A + ((size_t)(valid ? gm : 0) * K + kb + cc*8);
            } else {
                int gn = n0 + row; valid = gn < N;
                gp = W + ((size_t)(valid ? gn : 0) * K + kb + cc*8);
            }
            if (valid) CPA16(sa, gp);
            else       asm volatile("st.shared.v4.b32 [%0], {%1,%1,%1,%1};" :: "r"(sa), "r"(0u));
        }
        CPA_COMMIT();
    };

    stage_load(0, 0);
    if (NC > 1) stage_load(1, 1);

    for (int c = 0; c < NC; c++) {
        if (c + 2 < NC) {
            stage_load(c + 2, (c + 2) % 3);
            asm volatile("cp.async.wait_group 2;");
        } else if (c + 1 < NC) {
            asm volatile("cp.async.wait_group 1;");
        } else {
            asm volatile("cp.async.wait_group 0;");
        }
        __syncthreads();

        uint32_t ab = sb + (c % 3) * 20480;
        int g = lane >> 3, li = lane & 7;
        #pragma unroll
        for (int k16 = 0; k16 < 2; k16++) {
            uint32_t aH[4][4], bH[4][2];
            #pragma unroll
            for (int mt = 0; mt < 4; mt++) {
                int row = wm + mt*16 + (g & 1)*8 + li;
                uint32_t ad = ab + row*80 + k16*32 + (g >> 1)*16;
                LDSM4(aH[mt], ad);
            }
            #pragma unroll
            for (int np = 0; np < 2; np++) {
                int row = wn + np*16 + ((lane >= 16) ? 8 : 0) + li;
                uint32_t bd = ab + 10240 + row*80 + k16*32 + ((lane >> 3) & 1)*16;
                uint32_t t4[4];
                LDSM4(t4, bd);
                bH[np*2][0] = t4[0]; bH[np*2][1] = t4[1];
                bH[np*2+1][0] = t4[2]; bH[np*2+1][1] = t4[3];
            }
            #pragma unroll
            for (int mt = 0; mt < 4; mt++)
                #pragma unroll
                for (int nt = 0; nt < 4; nt++)
                    MMA16816(acc[mt][nt], aH[mt], bH[nt]);
        }
        __syncthreads();
    }

    // ---------------- epilogue ----------------
    int qr = lane >> 2, qc = (lane & 3) * 2;
    #pragma unroll
    for (int mt = 0; mt < 4; mt++) {
        #pragma unroll
        for (int half_ = 0; half_ < 2; half_++) {
            int m = m0 + wm + mt*16 + half_*8 + qr;
            if (m >= M) continue;
            #pragma unroll
            for (int nt = 0; nt < 4; nt++) {
                int cl = wn + nt*8 + qc;
                int n = n0 + cl;
                if (n >= N) continue;
                float v0 = acc[mt][nt][half_*2 + 0] + biass[cl];
                float v1 = acc[mt][nt][half_*2 + 1] + biass[cl + 1];
                if (MODE == 5) {
                    *(__half2*)(Ch + (size_t)m * N + n) = __floats2half2_rn(v0, v1);
                } else if (MODE == 1) {
                    __half2 p = __floats2half2_rn(fmaxf(v0, 0.f), fmaxf(v1, 0.f));
                    *(__half2*)(Ch + (size_t)m * N + n) = p;
                } else if (MODE == 2) {
                    int lq = m >> 3, b = m & 7;
                    int part = n >> 8, h = (n >> 5) & 7, d = n & 31;
                    size_t o = ((((size_t)lq * NH_ + h) * 8) + b) * HD_ + d;
                    __half* dstb = (part == 0) ? g_Q : (part == 1) ? g_K : g_Vv;
                    *(__half2*)(dstb + o) = __floats2half2_rn(v0, v1);
                } else if (MODE == 3) {
                    int b = m / LIN_, lin = m - b * LIN_;
                    int h = n >> 5, d = n & 31;
                    size_t o = (((size_t)(b*NH_ + h)) * LIN_ + lin) * HD_ + d;
                    *(__half2*)(g_val + o) = __floats2half2_rn(v0, v1);
                } else { // MODE 4
                    if (n < 192)
                        *(float2*)(g_off + (size_t)m * 192 + n) = make_float2(v0, v1);
                    else
                        *(float2*)(g_aw + (size_t)m * 96 + (n - 192)) = make_float2(v0, v1);
                }
            }
        }
    }
}

// ---------------- self-attention over the 8-token axis ----------------
#define ALQ 2
__global__ void __launch_bounds__(128)
attn_kernel()
{
    __shared__ float Ks[ALQ * NH_ * 8 * HD_];
    __shared__ float Vs[ALQ * NH_ * 8 * HD_];

    int lq0 = blockIdx.x * ALQ;
    int t = threadIdx.x;

    const uint4* kg = (const uint4*)(g_K  + (size_t)lq0 * NH_ * 8 * HD_);
    const uint4* vg = (const uint4*)(g_Vv + (size_t)lq0 * NH_ * 8 * HD_);
    #pragma unroll
    for (int f = 0; f < (ALQ * NH_ * 8 * HD_ / 8) / 128; f++) {
        int idx = f * 128 + t;
        uint4 kv = kg[idx], vv = vg[idx];
        const __half2* kh = (const __half2*)&kv;
        const __half2* vh = (const __half2*)&vv;
        float* kd = Ks + idx * 8;
        float* vd = Vs + idx * 8;
        #pragma unroll
        for (int j = 0; j < 4; j++) {
            float2 a = __half22float2(kh[j]); kd[2*j] = a.x; kd[2*j+1] = a.y;
            float2 b = __half22float2(vh[j]); vd[2*j] = b.x; vd[2*j+1] = b.y;
        }
    }
    __syncthreads();

    int lql = t >> 6;
    int r   = t & 63;
    int h   = r >> 3;
    int s   = r & 7;
    int lq  = lq0 + lql;

    const float scale = 0.17677669529663687f;
    float qr[HD_];
    {
        const uint4* Qp = (const uint4*)(g_Q + ((((size_t)lq * NH_ + h) * 8) + s) * HD_);
        #pragma unroll
        for (int i = 0; i < 4; i++) {
            uint4 q4 = Qp[i];
            const __half2* qh = (const __half2*)&q4;
            #pragma unroll
            for (int j = 0; j < 4; j++) {
                float2 a = __half22float2(qh[j]);
                qr[i*8 + 2*j] = a.x; qr[i*8 + 2*j + 1] = a.y;
            }
        }
    }

    const float* Kt = Ks + (lql * NH_ + h) * 8 * HD_;
    const float* Vt = Vs + (lql * NH_ + h) * 8 * HD_;

    float logit[8];
    float mx = -1e30f;
    #pragma unroll
    for (int j = 0; j < 8; j++) {
        float acc = 0.f;
        const float* kp = Kt + j * HD_;
        #pragma unroll
        for (int d = 0; d < HD_; d++) acc = fmaf(qr[d], kp[d], acc);
        logit[j] = acc * scale;
        mx = fmaxf(mx, logit[j]);
    }
    float sum = 0.f;
    #pragma unroll
    for (int j = 0; j < 8; j++) { logit[j] = __expf(logit[j] - mx); sum += logit[j]; }
    float inv = 1.f / sum;

    float accv[HD_];
    #pragma unroll
    for (int d = 0; d < HD_; d++) accv[d] = 0.f;
    #pragma unroll
    for (int j = 0; j < 8; j++) {
        float p = logit[j] * inv;
        const float* vp = Vt + j * HD_;
        #pragma unroll
        for (int d = 0; d < HD_; d++) accv[d] = fmaf(p, vp[d], accv[d]);
    }

    __half* oh = g_act + OFF_CTX + ((size_t)(lq * B_ + s)) * D_ + h * HD_;
    #pragma unroll
    for (int d = 0; d < HD_; d += 2)
        *(__half2*)(oh + d) = __floats2half2_rn(accv[d], accv[d+1]);
}

// ---------------- LayerNorm(x1 + x2) on fp16 inputs ----------------
// writes fp16 (oh, nullable) and/or fp32 (of, nullable)
__global__ void __launch_bounds__(256)
ln_kernel(const __half* __restrict__ x1, const __half* __restrict__ x2,
          const float* __restrict__ gam, const float* __restrict__ bet,
          __half* __restrict__ oh, float* __restrict__ of)
{
    int gwarp = (blockIdx.x * blockDim.x + threadIdx.x) >> 5;
    int lane  = threadIdx.x & 31;
    if (gwarp >= ROWS_) return;
    size_t base = (size_t)gwarp * D_ + lane * 8;

    float v[8];
    {
        uint4 a4 = *(const uint4*)(x1 + base);
        uint4 b4 = *(const uint4*)(x2 + base);
        const __half2* ah = (const __half2*)&a4;
        const __half2* bh = (const __half2*)&b4;
        #pragma unroll
        for (int j = 0; j < 4; j++) {
            float2 a = __half22float2(ah[j]);
            float2 b = __half22float2(bh[j]);
            v[2*j]   = a.x + b.x;
            v[2*j+1] = a.y + b.y;
        }
    }
    float s = 0.f, ss = 0.f;
    #pragma unroll
    for (int j = 0; j < 8; j++) { s += v[j]; ss += v[j]*v[j]; }
    #pragma unroll
    for (int o = 16; o > 0; o >>= 1) {
        s  += __shfl_xor_sync(0xffffffffu, s,  o);
        ss += __shfl_xor_sync(0xffffffffu, ss, o);
    }
    float mean = s * (1.f/256.f);
    float var  = ss * (1.f/256.f) - mean*mean;
    float rstd = rsqrtf(var + 1e-5f);

    int c = lane * 8;
    float4 g0 = *(const float4*)(gam + c);
    float4 g1 = *(const float4*)(gam + c + 4);
    float4 e0 = *(const float4*)(bet + c);
    float4 e1 = *(const float4*)(bet + c + 4);
    float ov[8];
    ov[0] = (v[0]-mean)*rstd*g0.x + e0.x;
    ov[1] = (v[1]-mean)*rstd*g0.y + e0.y;
    ov[2] = (v[2]-mean)*rstd*g0.z + e0.z;
    ov[3] = (v[3]-mean)*rstd*g0.w + e0.w;
    ov[4] = (v[4]-mean)*rstd*g1.x + e1.x;
    ov[5] = (v[5]-mean)*rstd*g1.y + e1.y;
    ov[6] = (v[6]-mean)*rstd*g1.z + e1.z;
    ov[7] = (v[7]-mean)*rstd*g1.w + e1.w;

    if (oh) {
        __half2 p0 = __floats2half2_rn(ov[0], ov[1]);
        __half2 p1 = __floats2half2_rn(ov[2], ov[3]);
        __half2 p2 = __floats2half2_rn(ov[4], ov[5]);
        __half2 p3 = __floats2half2_rn(ov[6], ov[7]);
        *(uint4*)(oh + base) = make_uint4(*(uint32_t*)&p0, *(uint32_t*)&p1,
                                          *(uint32_t*)&p2, *(uint32_t*)&p3);
    }
    if (of) {
        *(float4*)(of + base)     = make_float4(ov[0], ov[1], ov[2], ov[3]);
        *(float4*)(of + base + 4) = make_float4(ov[4], ov[5], ov[6], ov[7]);
    }
}

// ---------------- MS-deformable sampling: 2 points per half-warp, half2 channels ----
__device__ __forceinline__ float2 samp2(const __half* __restrict__ vb,
                                        int y, int x, int W, int cl)
{
    if (x < 0 || x >= W || y < 0 || y >= W) return make_float2(0.f, 0.f);
    return __half22float2(*(const __half2*)(vb + ((size_t)(y * W + x)) * HD_ + 2*cl));
}

__global__ void __launch_bounds__(256)
msdeform_kernel()
{
    int gw = (blockIdx.x * blockDim.x + threadIdx.x) >> 5;
    int lane = threadIdx.x & 31;
    if (gw >= ROWS_ * NH_) return;
    int i = gw >> 3, h = gw & 7;
    int s = i >> 3, b = i & 7;
    int hv = lane >> 4;          // half-warp 0/1
    int cl = lane & 15;          // channel-pair index (channels 2cl, 2cl+1)

    float rx = ((s % 60) + 0.5f) * (1.f/60.f);
    float ry = ((s / 60) + 0.5f) * (1.f/60.f);

    const float* awp = g_aw + (size_t)i * 96 + h * 12;
    float mx = -1e30f;
    #pragma unroll
    for (int t = 0; t < 12; t++) mx = fmaxf(mx, awp[t]);
    float sm = 0.f;
    #pragma unroll
    for (int t = 0; t < 12; t++) sm += __expf(awp[t] - mx);
    float inv = 1.f / sm;

    const float* offp = g_off + (size_t)i * 192 + h * 24;
    const __half* vbase = g_val + (((size_t)(b*NH_ + h)) * LIN_) * HD_;

    float ax = 0.f, ay = 0.f;
    #pragma unroll
    for (int j = 0; j < 6; j++) {
        int t = 2*j + hv;
        int l = t >> 2;
        int Wl = 60 >> l;
        int St = (l >= 1 ? 3600 : 0) + (l >= 2 ? 900 : 0);
        float fWl = (float)Wl;
        float ox = offp[2*t], oy = offp[2*t + 1];
        float x = (rx + ox / fWl) * fWl - 0.5f;
        float y = (ry + oy / fWl) * fWl - 0.5f;
        float fx0 = floorf(x), fy0 = floorf(y);
        float fx = x - fx0, fy = y - fy0;
        int x0 = (int)fx0, y0 = (int)fy0;
        float a = __expf(awp[t] - mx) * inv;
        const __half* vb = vbase + (size_t)St * HD_;
        float2 s00 = samp2(vb, y0,   x0,   Wl, cl);
        float2 s01 = samp2(vb, y0,   x0+1, Wl, cl);
        float2 s10 = samp2(vb, y0+1, x0,   Wl, cl);
        float2 s11 = samp2(vb, y0+1, x0+1, Wl, cl);
        float w00 = (1.f-fx)*(1.f-fy), w01 = fx*(1.f-fy);
        float w10 = (1.f-fx)*fy,       w11 = fx*fy;
        float bx = s00.x*w00 + s01.x*w01 + s10.x*w10 + s11.x*w11;
        float by = s00.y*w00 + s01.y*w01 + s10.y*w10 + s11.y*w11;
        ax = fmaf(a, bx, ax);
        ay = fmaf(a, by, ay);
    }
    ax += __shfl_xor_sync(0xffffffffu, ax, 16);
    ay += __shfl_xor_sync(0xffffffffu, ay, 16);
    if (hv == 0)
        *(__half2*)(g_act + OFF_MS + (size_t)i * D_ + h * HD_ + 2*cl) = __floats2half2_rn(ax, ay);
}

// ---------------- host orchestration ----------------
extern "C" void kernel_launch(void* const* d_in, const int* in_sizes, int n_in,
                              void* d_out, int out_size)
{
    (void)in_sizes; (void)n_in; (void)out_size;
    const float* tgt  = (const float*)d_in[0];
    const float* qp   = (const float*)d_in[1];
    const float* src  = (const float*)d_in[2];
    const float* in_w = (const float*)d_in[5];
    const float* in_b = (const float*)d_in[6];
    const float* ow   = (const float*)d_in[7];
    const float* ob   = (const float*)d_in[8];
    const float* sow  = (const float*)d_in[9];
    const float* sob  = (const float*)d_in[10];
    const float* aww  = (const float*)d_in[11];
    const float* awb  = (const float*)d_in[12];
    const float* vw   = (const float*)d_in[13];
    const float* vb   = (const float*)d_in[14];
    const float* cow  = (const float*)d_in[15];
    const float* cob  = (const float*)d_in[16];
    const float* ln1g = (const float*)d_in[17];
    const float* ln1b = (const float*)d_in[18];
    const float* ln2g = (const float*)d_in[19];
    const float* ln2b = (const float*)d_in[20];
    const float* ln3g = (const float*)d_in[21];
    const float* ln3b = (const float*)d_in[22];
    const float* f1w  = (const float*)d_in[23];
    const float* f1b  = (const float*)d_in[24];
    const float* f2w  = (const float*)d_in[25];
    const float* f2b  = (const float*)d_in[26];
    float* out = (float*)d_out;

    __half *act, *whi, *tmph;
    float *cbp;
    cudaGetSymbolAddress((void**)&act,  g_act);
    cudaGetSymbolAddress((void**)&whi,  g_whi);
    cudaGetSymbolAddress((void**)&tmph, g_tmph);
    cudaGetSymbolAddress((void**)&cbp,  g_cball);

    cudaFuncSetAttribute(gemm_mma<1>, cudaFuncAttributeMaxDynamicSharedMemorySize, GSMEM);
    cudaFuncSetAttribute(gemm_mma<2>, cudaFuncAttributeMaxDynamicSharedMemorySize, GSMEM);
    cudaFuncSetAttribute(gemm_mma<3>, cudaFuncAttributeMaxDynamicSharedMemorySize, GSMEM);
    cudaFuncSetAttribute(gemm_mma<4>, cudaFuncAttributeMaxDynamicSharedMemorySize, GSMEM);
    cudaFuncSetAttribute(gemm_mma<5>, cudaFuncAttributeMaxDynamicSharedMemorySize, GSMEM);

    // ---- merged preprocessing ----
    PreArgs pa;
    pa.W[0]=in_w; pa.Bv[0]=in_b; pa.N[0]=768;  pa.K[0]=256;  pa.lim[0]=512;
    pa.W[1]=ow;   pa.Bv[1]=ob;   pa.N[1]=256;  pa.K[1]=256;  pa.lim[1]=0;
    pa.W[2]=vw;   pa.Bv[2]=vb;   pa.N[2]=256;  pa.K[2]=256;  pa.lim[2]=0;
    pa.W[3]=sow;  pa.Bv[3]=sob;  pa.N[3]=192;  pa.K[3]=256;  pa.lim[3]=192;
    pa.W[4]=aww;  pa.Bv[4]=awb;  pa.N[4]=96;   pa.K[4]=256;  pa.lim[4]=96;
    pa.W[5]=cow;  pa.Bv[5]=cob;  pa.N[5]=256;  pa.K[5]=256;  pa.lim[5]=0;
    pa.W[6]=f1w;  pa.Bv[6]=f1b;  pa.N[6]=1024; pa.K[6]=256;  pa.lim[6]=0;
    pa.W[7]=f2w;  pa.Bv[7]=f2b;  pa.N[7]=256;  pa.K[7]=1024; pa.lim[7]=0;
    pa.qp = qp; pa.tgt = tgt; pa.src = src;
    pre_kernel<<<NB_CVTA + NB_CVTW + NB_CB, 256>>>(pa);

    const int MT  = 225;   // 28800/128
    const int VMT = 296;   // ceil(37800/128)

    // 1) QKV projection (qp folded into Q/K bias), fp16 scatter
    gemm_mma<2><<<dim3(MT, 6), 256, GSMEM>>>(act+OFF_TGT, whi+WOFF_IN,
                                             nullptr, cbp+0*1024, ROWS_, 768, 256);
    // 2) tiny self-attention
    attn_kernel<<<LQ_/ALQ, 128>>>();
    // 3) out projection (fp16) + ln2 (fp16 residual)
    gemm_mma<5><<<dim3(MT, 2), 256, GSMEM>>>(act+OFF_CTX, whi+WOFF_OW,
                                             tmph, cbp+1*1024, ROWS_, 256, 256);
    ln_kernel<<<ROWS_/8, 256>>>(act+OFF_TGT, tmph, ln2g, ln2b, act+OFF_T, nullptr);
    // 4) value projection (fp16 scatter) + merged off/aw GEMM (N=288)
    gemm_mma<3><<<dim3(VMT, 2), 256, GSMEM>>>(act+OFF_SRC, whi+WOFF_VW,
                                              nullptr, cbp+2*1024, VROWS_, 256, 256);
    gemm_mma<4><<<dim3(MT, 3), 256, GSMEM>>>(act+OFF_T, whi+WOFF_SOW,
                                             nullptr, cbp+3*1024, ROWS_, 288, 256);
    // 5) sampling + cross projection + ln1
    msdeform_kernel<<<ROWS_, 256>>>();
    gemm_mma<5><<<dim3(MT, 2), 256, GSMEM>>>(act+OFF_MS, whi+WOFF_COW,
                                             tmph, cbp+5*1024, ROWS_, 256, 256);
    ln_kernel<<<ROWS_/8, 256>>>(act+OFF_T, tmph, ln1g, ln1b, act+OFF_TQ, nullptr);
    // 6) FFN + ln3 (final fp32 output)
    gemm_mma<1><<<dim3(MT, 8), 256, GSMEM>>>(act+OFF_TQ, whi+WOFF_F1,
                                             act+OFF_FFN, cbp+6*1024, ROWS_, 1024, 256);
    gemm_mma<5><<<dim3(MT, 2), 256, GSMEM>>>(act+OFF_FFN, whi+WOFF_F2,
                                             tmph, cbp+7*1024, ROWS_, 256, 1024);
    ln_kernel<<<ROWS_/8, 256>>>(act+OFF_TQ, tmph, ln3g, ln3b, nullptr, out);
}